// round 12
// baseline (speedup 1.0000x reference)
#include <cuda_runtime.h>
#include <cuda_bf16.h>
#include <math.h>

typedef unsigned long long u64;
typedef unsigned int u32;

__device__ __forceinline__ unsigned smem_u32p(const void* p) {
    unsigned a;
    asm("{ .reg .u64 t; cvta.to.shared.u64 t, %1; cvt.u32.u64 %0, t; }" : "=r"(a) : "l"(p));
    return a;
}
__device__ __forceinline__ void cp16(unsigned dst, const void* src) {
    asm volatile("cp.async.cg.shared.global [%0], [%1], 16;" :: "r"(dst), "l"(src));
}
__device__ __forceinline__ void cp4(unsigned dst, const void* src) {
    asm volatile("cp.async.ca.shared.global [%0], [%1], 4;" :: "r"(dst), "l"(src));
}
__device__ __forceinline__ void cp_commit() { asm volatile("cp.async.commit_group;"); }
template <int Nw>
__device__ __forceinline__ void cp_wait() { asm volatile("cp.async.wait_group %0;" :: "n"(Nw)); }

// Problem constants
constexpr int N   = 8;
constexpr int C   = 128;
constexpr int CW  = 64;
constexpr int CIN = C + CW;   // 192
constexpr int H   = 96;
constexpr int W   = 96;
constexpr int HW  = H * W;    // 9216
constexpr int K768 = C * 6;   // 768

// Static scratch
__device__ float g_bases[N * 54 * HW];
__device__ float g_v    [(size_t)N * K768 * HW];
__device__ __align__(16) u32 g_ahi [K768 * 64];
__device__ __align__(16) u32 g_alo [K768 * 64];
__device__ __align__(16) u32 g_w1hi[9 * 96 * 128];
__device__ __align__(16) u32 g_w1lo[9 * 96 * 128];
// pre-split, pre-padded inputs: [n][96 ci2][98 rows][104 cols]
constexpr int IN_CI = 96;
constexpr int IN_R  = 98;
constexpr int IN_CSTR = 104;
constexpr int IN_NSTR = IN_CI * IN_R * IN_CSTR;
__device__ __align__(16) u32 g_inhi[N * IN_NSTR];
__device__ __align__(16) u32 g_inlo[N * IN_NSTR];

// ===========================================================================
__device__ __forceinline__ void split2(float f0, float f1, u32& hi, u32& lo) {
    __nv_bfloat16 h0 = __float2bfloat16_rn(f0);
    __nv_bfloat16 h1 = __float2bfloat16_rn(f1);
    float l0f = f0 - __bfloat162float(h0);
    float l1f = f1 - __bfloat162float(h1);
    __nv_bfloat16 l0 = __float2bfloat16_rn(l0f);
    __nv_bfloat16 l1 = __float2bfloat16_rn(l1f);
    hi = ((u32)__bfloat16_as_ushort(h1) << 16) | (u32)__bfloat16_as_ushort(h0);
    lo = ((u32)__bfloat16_as_ushort(l1) << 16) | (u32)__bfloat16_as_ushort(l0);
}

__device__ __forceinline__ void mma_bf16(float d[4], const u32 a[4], u32 b0, u32 b1) {
    asm volatile(
        "mma.sync.aligned.m16n8k16.row.col.f32.bf16.bf16.f32 "
        "{%0,%1,%2,%3}, {%4,%5,%6,%7}, {%8,%9}, {%0,%1,%2,%3};"
        : "+f"(d[0]), "+f"(d[1]), "+f"(d[2]), "+f"(d[3])
        : "r"(a[0]), "r"(a[1]), "r"(a[2]), "r"(a[3]), "r"(b0), "r"(b1));
}

// ===========================================================================
// prep kernels
// ===========================================================================
__global__ __launch_bounds__(256) void k_prep_a(const float* __restrict__ coef)
{
    const int idx = blockIdx.x * 256 + threadIdx.x;
    const int rg = idx >> 6;
    const int k2 = idx & 63;
    const int c  = rg / 6;
    const int mm = rg - c * 6;
    const int k  = 2 * k2;
    u32 hi, lo;
    split2(coef[c * K768 + k * 6 + mm], coef[c * K768 + (k + 1) * 6 + mm], hi, lo);
    g_ahi[idx] = hi;
    g_alo[idx] = lo;
}

__global__ __launch_bounds__(512) void k_prep_w1(const float* __restrict__ w1)
{
    const int idx = blockIdx.x * 512 + threadIdx.x;
    const int tap = idx / (96 * 128);
    const int rem = idx - tap * 96 * 128;
    const int ci2 = rem >> 7;
    const int co  = rem & 127;
    const float f0 = w1[(co * CIN + 2 * ci2)     * 9 + tap];
    const float f1 = w1[(co * CIN + 2 * ci2 + 1) * 9 + tap];
    u32 hi, lo;
    split2(f0, f1, hi, lo);
    g_w1hi[idx] = hi;
    g_w1lo[idx] = lo;
}

__global__ __launch_bounds__(512) void k_prep_in(
    const float* __restrict__ feat, const float* __restrict__ wgt)
{
    const int idx = blockIdx.x * 512 + threadIdx.x;
    const int n   = idx / IN_NSTR;
    int rem = idx - n * IN_NSTR;
    const int ci2 = rem / (IN_R * IN_CSTR);
    rem -= ci2 * (IN_R * IN_CSTR);
    const int row = rem / IN_CSTR;
    const int col = rem - row * IN_CSTR;
    float f0 = 0.f, f1 = 0.f;
    if (row >= 1 && row <= 96 && col >= 1 && col <= 96) {
        const int y = row - 1, x = col - 1;
        const float* b = (ci2 < 64)
            ? &feat[((n * C + 2 * ci2) * H + y) * W + x]
            : &wgt [((n * CW + 2 * (ci2 - 64)) * H + y) * W + x];
        f0 = b[0];
        f1 = b[HW];
    }
    u32 hi, lo;
    split2(f0, f1, hi, lo);
    g_inhi[idx] = hi;
    g_inlo[idx] = lo;
}

// ===========================================================================
// conv1 mma (unchanged from R11)
// ===========================================================================
constexpr int CISTR = 424;
constexpr int IHALF = 24 * CISTR;
constexpr int IBSZ  = 2 * IHALF;
constexpr int AB    = 2 * IBSZ;
constexpr int ASTR  = 136;
constexpr int ATILE = 24 * ASTR;
constexpr int SM_U32  = AB + 4 * ATILE;
constexpr int SM_BYTES = SM_U32 * 4;       // 215040 B

__global__ __launch_bounds__(512, 1) void k_conv1_mma(
    const float* __restrict__ b1,
    const float* __restrict__ w2,   const float* __restrict__ b2,
    const float* __restrict__ bbuf)
{
    extern __shared__ u32 sm[];
    const int tid  = threadIdx.x;
    const int wid  = tid >> 5;
    const int lane = tid & 31;
    const int wm = wid & 3;
    const int wn = wid >> 2;
    const int r  = lane >> 2;
    const int q  = lane & 3;

    const int n  = blockIdx.z;
    const int y0 = blockIdx.y * 2;

    float d[2][6][4];
    #pragma unroll
    for (int mi = 0; mi < 2; mi++)
        #pragma unroll
        for (int ni = 0; ni < 6; ni++)
            #pragma unroll
            for (int e = 0; e < 4; e++) d[mi][ni][e] = 0.f;

    auto stageA = [&](int tap, int cg, int buf) {
        const u32* srcH = g_w1hi + (tap * 96 + cg * 24) * 128;
        const u32* srcL = g_w1lo + (tap * 96 + cg * 24) * 128;
        u32* dH = sm + AB + buf * 2 * ATILE;
        u32* dL = dH + ATILE;
        #pragma unroll
        for (int it = 0; it < 2; it++) {
            int i = tid + it * 512;
            if (i < 768) {
                int ci2l = i >> 5;
                int c4   = (i & 31) * 4;
                cp16(smem_u32p(&dH[ci2l * ASTR + c4]), &srcH[ci2l * 128 + c4]);
                cp16(smem_u32p(&dL[ci2l * ASTR + c4]), &srcL[ci2l * 128 + c4]);
            }
        }
    };

    auto stageInRange = [&](int cgT, int buf, int c0, int c1) {
        const int ibase = buf * IBSZ;
        const int cnt = (c1 - c0) * 200;
        for (int i = tid; i < cnt; i += 512) {
            int ci2o = i / 200;
            int rem  = i - ci2o * 200;
            int arr  = rem / 100;
            int rem2 = rem - arr * 100;
            int rr   = rem2 / 25;
            int f4   = rem2 - rr * 25;
            int dst  = ibase + arr * IHALF + (c0 + ci2o) * CISTR + rr * 100 + f4 * 4;
            int src  = ((n * IN_CI + cgT * 24 + c0 + ci2o) * IN_R + y0 + rr) * IN_CSTR + f4 * 4;
            cp16(smem_u32p(&sm[dst]), arr ? &g_inlo[src] : &g_inhi[src]);
        }
    };

    stageInRange(0, 0, 0, 24);
    stageA(0, 0, 0);
    cp_commit();

    const int prow = wn >> 1;
    const int px0  = (wn & 1) * 48;

    int it = 0;
    for (int cg = 0; cg < 4; cg++) {
        const int ib = (cg & 1) * IBSZ;
        for (int tap = 0; tap < 9; tap++, it++) {
            const int abuf = it & 1;
            __syncthreads();
            if (tap >= 2 && tap <= 5 && cg < 3)
                stageInRange(cg + 1, (cg + 1) & 1, (tap - 2) * 6, (tap - 1) * 6);
            if (it + 1 < 36) {
                stageA((it + 1) % 9, (it + 1) / 9, abuf ^ 1);
                cp_commit();
                cp_wait<1>();
            } else {
                cp_wait<0>();
            }
            __syncthreads();

            const int ky = tap / 3, kx = tap % 3;
            const u32* AH = sm + AB + abuf * 2 * ATILE;
            const u32* AL = AH + ATILE;
            const int boff = (prow + ky) * 100 + kx + px0;

            #pragma unroll
            for (int s = 0; s < 3; s++) {
                const int kb2 = s * 8;
                u32 ahi[2][4], alo[2][4];
                #pragma unroll
                for (int mi = 0; mi < 2; mi++) {
                    const int ra = wm * 32 + mi * 16 + r;
                    ahi[mi][0] = AH[(kb2 + q) * ASTR + ra];
                    ahi[mi][1] = AH[(kb2 + q) * ASTR + ra + 8];
                    ahi[mi][2] = AH[(kb2 + 4 + q) * ASTR + ra];
                    ahi[mi][3] = AH[(kb2 + 4 + q) * ASTR + ra + 8];
                    alo[mi][0] = AL[(kb2 + q) * ASTR + ra];
                    alo[mi][1] = AL[(kb2 + q) * ASTR + ra + 8];
                    alo[mi][2] = AL[(kb2 + 4 + q) * ASTR + ra];
                    alo[mi][3] = AL[(kb2 + 4 + q) * ASTR + ra + 8];
                }
                #pragma unroll
                for (int ni = 0; ni < 6; ni++) {
                    const int a0 = (kb2 + q) * CISTR + boff + ni * 8 + r;
                    const int a1 = (kb2 + 4 + q) * CISTR + boff + ni * 8 + r;
                    const u32 bhi0 = sm[ib + a0];
                    const u32 bhi1 = sm[ib + a1];
                    const u32 blo0 = sm[ib + IHALF + a0];
                    const u32 blo1 = sm[ib + IHALF + a1];
                    #pragma unroll
                    for (int mi = 0; mi < 2; mi++) {
                        mma_bf16(d[mi][ni], ahi[mi], bhi0, bhi1);
                        mma_bf16(d[mi][ni], ahi[mi], blo0, blo1);
                        mma_bf16(d[mi][ni], alo[mi], bhi0, bhi1);
                    }
                }
            }
        }
    }
    __syncthreads();

    float* sH = reinterpret_cast<float*>(sm);
    #pragma unroll
    for (int mi = 0; mi < 2; mi++) {
        const int row = wm * 32 + mi * 16 + r;
        const float bb0 = b1[row];
        const float bb1 = b1[row + 8];
        #pragma unroll
        for (int ni = 0; ni < 6; ni++) {
            const int px = prow * 96 + px0 + ni * 8 + 2 * q;
            sH[row * 194 + px]           = tanhf(d[mi][ni][0] + bb0);
            sH[row * 194 + px + 1]       = tanhf(d[mi][ni][1] + bb0);
            sH[(row + 8) * 194 + px]     = tanhf(d[mi][ni][2] + bb1);
            sH[(row + 8) * 194 + px + 1] = tanhf(d[mi][ni][3] + bb1);
        }
    }
    __syncthreads();

    float* sW2 = reinterpret_cast<float*>(sm) + 24832;
    float* sBv = reinterpret_cast<float*>(sm) + 29440;
    float* sBB = reinterpret_cast<float*>(sm) + 36544;
    #pragma unroll
    for (int itr = 0; itr < 9; itr++) {
        int i = tid + itr * 512;
        int ci = i / 36;
        int ch = i - ci * 36;
        sW2[i] = w2[ch * 128 + ci];
    }
    if (tid < 54) sBB[tid] = bbuf[tid];
    __syncthreads();

    if (tid < 384) {
        const int px  = tid >> 1;
        const int ch0 = (tid & 1) * 18;
        float a2c[18];
        #pragma unroll
        for (int qq = 0; qq < 18; qq++) a2c[qq] = 0.f;
        for (int ci = 0; ci < 128; ci++) {
            const float hv = sH[ci * 194 + px];
            const float* wr = &sW2[ci * 36 + ch0];
            #pragma unroll
            for (int qq = 0; qq < 18; qq++)
                a2c[qq] = fmaf(wr[qq], hv, a2c[qq]);
        }
        #pragma unroll
        for (int qq = 0; qq < 18; qq++)
            sBv[px * 37 + ch0 + qq] = tanhf(a2c[qq] + b2[ch0 + qq]);
    }
    __syncthreads();

    for (int i = tid; i < 54 * 192; i += 512) {
        const int j  = i / 192;
        const int px = i - j * 192;
        const int row = px / 96;
        const int x   = px - row * 96;
        const int m  = j / 9;
        const int l  = j - m * 9;
        float s = 0.f;
        #pragma unroll
        for (int t = 0; t < 6; t++)
            s = fmaf(sBv[px * 37 + m * 6 + t], sBB[t * 9 + l], s);
        g_bases[(n * 54 + j) * HW + (y0 + row) * W + x] = s;
    }
}

// ===========================================================================
// V-GEMM v4: K split into 2 chunks of 64, double-buffered cp.async pipeline.
// PAD2 = 36 layout (bank = 4*row + q, conflict-free fragments).
// ===========================================================================
constexpr int PAD2 = 36;
constexpr int VCH  = 128 * PAD2;            // 4608 u32 per array per chunk
constexpr int VCHUNK = 4 * VCH;             // AHI, ALO, BHI, BLO
constexpr int VG_SMEM = 2 * VCHUNK * 4;     // 147456 B

__global__ __launch_bounds__(512, 1) void k_vgemm_mma()
{
    extern __shared__ u32 vsm[];
    const int tid = threadIdx.x;
    const int n  = blockIdx.z;
    const int r0 = blockIdx.y * 128;
    const int p0 = blockIdx.x * 128;

    auto stage = [&](int c) {
        u32* sAhi = vsm + c * VCHUNK;
        u32* sAlo = sAhi + VCH;
        u32* sBhi = sAlo + VCH;
        u32* sBlo = sBhi + VCH;
        // A: 128 m x 32 k2 (8 float4) per array
        #pragma unroll
        for (int it = 0; it < 2; it++) {
            int i = tid + it * 512;            // < 1024
            int m  = i >> 3;
            int k4 = i & 7;
            cp16(smem_u32p(&sAhi[m * PAD2 + k4 * 4]),
                 &g_ahi[(r0 + m) * 64 + c * 32 + k4 * 4]);
            cp16(smem_u32p(&sAlo[m * PAD2 + k4 * 4]),
                 &g_alo[(r0 + m) * 64 + c * 32 + k4 * 4]);
        }
        // B: 32 k2 x 128 p, cp4 transposed gather from padded split input
        #pragma unroll
        for (int it = 0; it < 8; it++) {
            int idx = tid + it * 512;          // < 4096
            int k2l = idx >> 7;
            int p   = idx & 127;
            int gp  = p0 + p;
            int row = gp / 96;
            int col = gp - row * 96;
            int src = ((n * IN_CI + c * 32 + k2l) * IN_R + row + 1) * IN_CSTR + col + 1;
            cp4(smem_u32p(&sBhi[p * PAD2 + k2l]), &g_inhi[src]);
            cp4(smem_u32p(&sBlo[p * PAD2 + k2l]), &g_inlo[src]);
        }
    };

    const int wid = tid >> 5;
    const int lane = tid & 31;
    const int wm = wid & 3;
    const int wn = wid >> 2;
    const int r  = lane >> 2;
    const int q  = lane & 3;

    float d[2][4][4];
    #pragma unroll
    for (int mi = 0; mi < 2; mi++)
        #pragma unroll
        for (int ni = 0; ni < 4; ni++)
            #pragma unroll
            for (int e = 0; e < 4; e++) d[mi][ni][e] = 0.f;

    auto compute = [&](int c) {
        const u32* sAhi = vsm + c * VCHUNK;
        const u32* sAlo = sAhi + VCH;
        const u32* sBhi = sAlo + VCH;
        const u32* sBlo = sBhi + VCH;
        #pragma unroll
        for (int ks = 0; ks < 4; ks++) {
            const int kc = ks * 8;
            u32 ahi[2][4], alo[2][4];
            #pragma unroll
            for (int mi = 0; mi < 2; mi++) {
                const int ra = wm * 32 + mi * 16 + r;
                ahi[mi][0] = sAhi[ra * PAD2 + kc + q];
                ahi[mi][1] = sAhi[(ra + 8) * PAD2 + kc + q];
                ahi[mi][2] = sAhi[ra * PAD2 + kc + 4 + q];
                ahi[mi][3] = sAhi[(ra + 8) * PAD2 + kc + 4 + q];
                alo[mi][0] = sAlo[ra * PAD2 + kc + q];
                alo[mi][1] = sAlo[(ra + 8) * PAD2 + kc + q];
                alo[mi][2] = sAlo[ra * PAD2 + kc + 4 + q];
                alo[mi][3] = sAlo[(ra + 8) * PAD2 + kc + 4 + q];
            }
            #pragma unroll
            for (int ni = 0; ni < 4; ni++) {
                const int nb = wn * 32 + ni * 8 + r;
                u32 bhi0 = sBhi[nb * PAD2 + kc + q];
                u32 bhi1 = sBhi[nb * PAD2 + kc + 4 + q];
                u32 blo0 = sBlo[nb * PAD2 + kc + q];
                u32 blo1 = sBlo[nb * PAD2 + kc + 4 + q];
                #pragma unroll
                for (int mi = 0; mi < 2; mi++) {
                    mma_bf16(d[mi][ni], ahi[mi], bhi0, bhi1);
                    mma_bf16(d[mi][ni], ahi[mi], blo0, blo1);
                    mma_bf16(d[mi][ni], alo[mi], bhi0, bhi1);
                }
            }
        }
    };

    stage(0);
    cp_commit();
    stage(1);
    cp_commit();
    cp_wait<1>();
    __syncthreads();
    compute(0);
    cp_wait<0>();
    __syncthreads();
    compute(1);

    float* Vn = g_v + (size_t)n * K768 * HW;
    #pragma unroll
    for (int mi = 0; mi < 2; mi++) {
        const int row = r0 + wm * 32 + mi * 16 + r;
        #pragma unroll
        for (int ni = 0; ni < 4; ni++) {
            const int col = p0 + wn * 32 + ni * 8 + 2 * q;
            *reinterpret_cast<float2*>(&Vn[(size_t)row * HW + col]) =
                make_float2(d[mi][ni][0], d[mi][ni][1]);
            *reinterpret_cast<float2*>(&Vn[(size_t)(row + 8) * HW + col]) =
                make_float2(d[mi][ni][2], d[mi][ni][3]);
        }
    }
}

// ===========================================================================
// combine v3: 8 channels per block (grid.y = 16), m-outer loop.
// ===========================================================================
__global__ __launch_bounds__(256) void k_combine(
    const float* __restrict__ bias, float* __restrict__ out)
{
    const int p  = blockIdx.x * 256 + threadIdx.x;
    const int cb = blockIdx.y * 8;
    const int n  = p / HW;
    const int hw = p - n * HW;
    const int y  = hw / W;
    const int x  = hw - y * W;

    int  off[9];
    u32  okm = 0;
    #pragma unroll
    for (int l = 0; l < 9; l++) {
        const int dy = l / 3 - 1, dx = l % 3 - 1;
        const bool ok = (unsigned)(y + dy) < (unsigned)H && (unsigned)(x + dx) < (unsigned)W;
        off[l] = ok ? (dy * W + dx) : 0;
        okm |= (ok ? 1u : 0u) << l;
    }

    float acc[8];
    #pragma unroll
    for (int ci = 0; ci < 8; ci++) acc[ci] = 0.f;

    const float* Vn = g_v + (size_t)n * K768 * HW + hw;

    #pragma unroll
    for (int m = 0; m < 6; m++) {
        float bs[9];
        #pragma unroll
        for (int l = 0; l < 9; l++) {
            float t = __ldg(&g_bases[(n * 54 + m * 9 + l) * HW + hw]);
            bs[l] = (okm >> l & 1u) ? t : 0.f;
        }
        const float* Vm = Vn + (size_t)(cb * 6 + m) * HW;
        #pragma unroll
        for (int ci = 0; ci < 8; ci++) {
            const float* row = Vm + (size_t)(ci * 6) * HW;
            float s = 0.f;
            #pragma unroll
            for (int l = 0; l < 9; l++)
                s = fmaf(bs[l], __ldg(row + off[l]), s);
            acc[ci] += s;
        }
    }

    float* on = out + (size_t)n * C * HW + hw;
    #pragma unroll
    for (int ci = 0; ci < 8; ci++)
        on[(size_t)(cb + ci) * HW] = acc[ci] + __ldg(&bias[cb + ci]);
}

// ---------------------------------------------------------------------------
extern "C" void kernel_launch(void* const* d_in, const int* in_sizes, int n_in,
                              void* d_out, int out_size)
{
    const float* feat = (const float*)d_in[0];
    const float* wgt  = (const float*)d_in[1];
    const float* w1   = (const float*)d_in[2];
    const float* b1   = (const float*)d_in[3];
    const float* w2   = (const float*)d_in[4];
    const float* b2   = (const float*)d_in[5];
    const float* bbuf = (const float*)d_in[6];
    const float* coef = (const float*)d_in[7];
    const float* bias = (const float*)d_in[8];
    float* out = (float*)d_out;

    static bool attr_set = false;
    if (!attr_set) {
        cudaFuncSetAttribute(k_conv1_mma,
                             cudaFuncAttributeMaxDynamicSharedMemorySize, SM_BYTES);
        cudaFuncSetAttribute(k_vgemm_mma,
                             cudaFuncAttributeMaxDynamicSharedMemorySize, VG_SMEM);
        attr_set = true;
    }

    k_prep_in<<<(N * IN_NSTR) / 512, 512>>>(feat, wgt);
    k_prep_w1<<<(9 * 96 * 128) / 512, 512>>>(w1);
    k_prep_a<<<(K768 * 64) / 256, 256>>>(coef);

    dim3 g1(1, H / 2, N);
    k_conv1_mma<<<g1, 512, SM_BYTES>>>(b1, w2, b2, bbuf);

    dim3 g3(HW / 128, K768 / 128, N);
    k_vgemm_mma<<<g3, 512, VG_SMEM>>>();

    dim3 g4((N * HW) / 256, 16);
    k_combine<<<g4, 256>>>(bias, out);
}

// round 13
// speedup vs baseline: 1.0108x; 1.0108x over previous
#include <cuda_runtime.h>
#include <cuda_bf16.h>
#include <math.h>

typedef unsigned long long u64;
typedef unsigned int u32;

__device__ __forceinline__ unsigned smem_u32p(const void* p) {
    unsigned a;
    asm("{ .reg .u64 t; cvta.to.shared.u64 t, %1; cvt.u32.u64 %0, t; }" : "=r"(a) : "l"(p));
    return a;
}
__device__ __forceinline__ void cp16(unsigned dst, const void* src) {
    asm volatile("cp.async.cg.shared.global [%0], [%1], 16;" :: "r"(dst), "l"(src));
}
__device__ __forceinline__ void cp4(unsigned dst, const void* src) {
    asm volatile("cp.async.ca.shared.global [%0], [%1], 4;" :: "r"(dst), "l"(src));
}
__device__ __forceinline__ void cp_commit() { asm volatile("cp.async.commit_group;"); }
template <int Nw>
__device__ __forceinline__ void cp_wait() { asm volatile("cp.async.wait_group %0;" :: "n"(Nw)); }

// Problem constants
constexpr int N   = 8;
constexpr int C   = 128;
constexpr int CW  = 64;
constexpr int CIN = C + CW;   // 192
constexpr int H   = 96;
constexpr int W   = 96;
constexpr int HW  = H * W;    // 9216
constexpr int K768 = C * 6;   // 768

// Static scratch
__device__ float g_bases[N * 54 * HW];
__device__ float g_v    [(size_t)N * K768 * HW];
__device__ __align__(16) u32 g_ahi [K768 * 64];
__device__ __align__(16) u32 g_alo [K768 * 64];
__device__ __align__(16) u32 g_w1hi[9 * 96 * 128];
__device__ __align__(16) u32 g_w1lo[9 * 96 * 128];
// pre-split, pre-padded inputs: [n][96 ci2][98 rows][104 cols]
constexpr int IN_CI = 96;
constexpr int IN_R  = 98;
constexpr int IN_CSTR = 104;
constexpr int IN_NSTR = IN_CI * IN_R * IN_CSTR;
__device__ __align__(16) u32 g_inhi[N * IN_NSTR];
__device__ __align__(16) u32 g_inlo[N * IN_NSTR];

// ===========================================================================
__device__ __forceinline__ void split2(float f0, float f1, u32& hi, u32& lo) {
    __nv_bfloat16 h0 = __float2bfloat16_rn(f0);
    __nv_bfloat16 h1 = __float2bfloat16_rn(f1);
    float l0f = f0 - __bfloat162float(h0);
    float l1f = f1 - __bfloat162float(h1);
    __nv_bfloat16 l0 = __float2bfloat16_rn(l0f);
    __nv_bfloat16 l1 = __float2bfloat16_rn(l1f);
    hi = ((u32)__bfloat16_as_ushort(h1) << 16) | (u32)__bfloat16_as_ushort(h0);
    lo = ((u32)__bfloat16_as_ushort(l1) << 16) | (u32)__bfloat16_as_ushort(l0);
}

__device__ __forceinline__ void mma_bf16(float d[4], const u32 a[4], u32 b0, u32 b1) {
    asm volatile(
        "mma.sync.aligned.m16n8k16.row.col.f32.bf16.bf16.f32 "
        "{%0,%1,%2,%3}, {%4,%5,%6,%7}, {%8,%9}, {%0,%1,%2,%3};"
        : "+f"(d[0]), "+f"(d[1]), "+f"(d[2]), "+f"(d[3])
        : "r"(a[0]), "r"(a[1]), "r"(a[2]), "r"(a[3]), "r"(b0), "r"(b1));
}

// ===========================================================================
// prep kernels
// ===========================================================================
__global__ __launch_bounds__(256) void k_prep_a(const float* __restrict__ coef)
{
    const int idx = blockIdx.x * 256 + threadIdx.x;
    const int rg = idx >> 6;
    const int k2 = idx & 63;
    const int c  = rg / 6;
    const int mm = rg - c * 6;
    const int k  = 2 * k2;
    u32 hi, lo;
    split2(coef[c * K768 + k * 6 + mm], coef[c * K768 + (k + 1) * 6 + mm], hi, lo);
    g_ahi[idx] = hi;
    g_alo[idx] = lo;
}

__global__ __launch_bounds__(512) void k_prep_w1(const float* __restrict__ w1)
{
    const int idx = blockIdx.x * 512 + threadIdx.x;
    const int tap = idx / (96 * 128);
    const int rem = idx - tap * 96 * 128;
    const int ci2 = rem >> 7;
    const int co  = rem & 127;
    const float f0 = w1[(co * CIN + 2 * ci2)     * 9 + tap];
    const float f1 = w1[(co * CIN + 2 * ci2 + 1) * 9 + tap];
    u32 hi, lo;
    split2(f0, f1, hi, lo);
    g_w1hi[idx] = hi;
    g_w1lo[idx] = lo;
}

__global__ __launch_bounds__(512) void k_prep_in(
    const float* __restrict__ feat, const float* __restrict__ wgt)
{
    const int idx = blockIdx.x * 512 + threadIdx.x;
    const int n   = idx / IN_NSTR;
    int rem = idx - n * IN_NSTR;
    const int ci2 = rem / (IN_R * IN_CSTR);
    rem -= ci2 * (IN_R * IN_CSTR);
    const int row = rem / IN_CSTR;
    const int col = rem - row * IN_CSTR;
    float f0 = 0.f, f1 = 0.f;
    if (row >= 1 && row <= 96 && col >= 1 && col <= 96) {
        const int y = row - 1, x = col - 1;
        const float* b = (ci2 < 64)
            ? &feat[((n * C + 2 * ci2) * H + y) * W + x]
            : &wgt [((n * CW + 2 * (ci2 - 64)) * H + y) * W + x];
        f0 = b[0];
        f1 = b[HW];
    }
    u32 hi, lo;
    split2(f0, f1, hi, lo);
    g_inhi[idx] = hi;
    g_inlo[idx] = lo;
}

// ===========================================================================
// conv1 mma (R11 known-good, unchanged)
// ===========================================================================
constexpr int CISTR = 424;
constexpr int IHALF = 24 * CISTR;
constexpr int IBSZ  = 2 * IHALF;
constexpr int AB    = 2 * IBSZ;
constexpr int ASTR  = 136;
constexpr int ATILE = 24 * ASTR;
constexpr int SM_U32  = AB + 4 * ATILE;
constexpr int SM_BYTES = SM_U32 * 4;       // 215040 B

__global__ __launch_bounds__(512, 1) void k_conv1_mma(
    const float* __restrict__ b1,
    const float* __restrict__ w2,   const float* __restrict__ b2,
    const float* __restrict__ bbuf)
{
    extern __shared__ u32 sm[];
    const int tid  = threadIdx.x;
    const int wid  = tid >> 5;
    const int lane = tid & 31;
    const int wm = wid & 3;
    const int wn = wid >> 2;
    const int r  = lane >> 2;
    const int q  = lane & 3;

    const int n  = blockIdx.z;
    const int y0 = blockIdx.y * 2;

    float d[2][6][4];
    #pragma unroll
    for (int mi = 0; mi < 2; mi++)
        #pragma unroll
        for (int ni = 0; ni < 6; ni++)
            #pragma unroll
            for (int e = 0; e < 4; e++) d[mi][ni][e] = 0.f;

    auto stageA = [&](int tap, int cg, int buf) {
        const u32* srcH = g_w1hi + (tap * 96 + cg * 24) * 128;
        const u32* srcL = g_w1lo + (tap * 96 + cg * 24) * 128;
        u32* dH = sm + AB + buf * 2 * ATILE;
        u32* dL = dH + ATILE;
        #pragma unroll
        for (int it = 0; it < 2; it++) {
            int i = tid + it * 512;
            if (i < 768) {
                int ci2l = i >> 5;
                int c4   = (i & 31) * 4;
                cp16(smem_u32p(&dH[ci2l * ASTR + c4]), &srcH[ci2l * 128 + c4]);
                cp16(smem_u32p(&dL[ci2l * ASTR + c4]), &srcL[ci2l * 128 + c4]);
            }
        }
    };

    auto stageInRange = [&](int cgT, int buf, int c0, int c1) {
        const int ibase = buf * IBSZ;
        const int cnt = (c1 - c0) * 200;
        for (int i = tid; i < cnt; i += 512) {
            int ci2o = i / 200;
            int rem  = i - ci2o * 200;
            int arr  = rem / 100;
            int rem2 = rem - arr * 100;
            int rr   = rem2 / 25;
            int f4   = rem2 - rr * 25;
            int dst  = ibase + arr * IHALF + (c0 + ci2o) * CISTR + rr * 100 + f4 * 4;
            int src  = ((n * IN_CI + cgT * 24 + c0 + ci2o) * IN_R + y0 + rr) * IN_CSTR + f4 * 4;
            cp16(smem_u32p(&sm[dst]), arr ? &g_inlo[src] : &g_inhi[src]);
        }
    };

    stageInRange(0, 0, 0, 24);
    stageA(0, 0, 0);
    cp_commit();

    const int prow = wn >> 1;
    const int px0  = (wn & 1) * 48;

    int it = 0;
    for (int cg = 0; cg < 4; cg++) {
        const int ib = (cg & 1) * IBSZ;
        for (int tap = 0; tap < 9; tap++, it++) {
            const int abuf = it & 1;
            __syncthreads();
            if (tap >= 2 && tap <= 5 && cg < 3)
                stageInRange(cg + 1, (cg + 1) & 1, (tap - 2) * 6, (tap - 1) * 6);
            if (it + 1 < 36) {
                stageA((it + 1) % 9, (it + 1) / 9, abuf ^ 1);
                cp_commit();
                cp_wait<1>();
            } else {
                cp_wait<0>();
            }
            __syncthreads();

            const int ky = tap / 3, kx = tap % 3;
            const u32* AH = sm + AB + abuf * 2 * ATILE;
            const u32* AL = AH + ATILE;
            const int boff = (prow + ky) * 100 + kx + px0;

            #pragma unroll
            for (int s = 0; s < 3; s++) {
                const int kb2 = s * 8;
                u32 ahi[2][4], alo[2][4];
                #pragma unroll
                for (int mi = 0; mi < 2; mi++) {
                    const int ra = wm * 32 + mi * 16 + r;
                    ahi[mi][0] = AH[(kb2 + q) * ASTR + ra];
                    ahi[mi][1] = AH[(kb2 + q) * ASTR + ra + 8];
                    ahi[mi][2] = AH[(kb2 + 4 + q) * ASTR + ra];
                    ahi[mi][3] = AH[(kb2 + 4 + q) * ASTR + ra + 8];
                    alo[mi][0] = AL[(kb2 + q) * ASTR + ra];
                    alo[mi][1] = AL[(kb2 + q) * ASTR + ra + 8];
                    alo[mi][2] = AL[(kb2 + 4 + q) * ASTR + ra];
                    alo[mi][3] = AL[(kb2 + 4 + q) * ASTR + ra + 8];
                }
                #pragma unroll
                for (int ni = 0; ni < 6; ni++) {
                    const int a0 = (kb2 + q) * CISTR + boff + ni * 8 + r;
                    const int a1 = (kb2 + 4 + q) * CISTR + boff + ni * 8 + r;
                    const u32 bhi0 = sm[ib + a0];
                    const u32 bhi1 = sm[ib + a1];
                    const u32 blo0 = sm[ib + IHALF + a0];
                    const u32 blo1 = sm[ib + IHALF + a1];
                    #pragma unroll
                    for (int mi = 0; mi < 2; mi++) {
                        mma_bf16(d[mi][ni], ahi[mi], bhi0, bhi1);
                        mma_bf16(d[mi][ni], ahi[mi], blo0, blo1);
                        mma_bf16(d[mi][ni], alo[mi], bhi0, bhi1);
                    }
                }
            }
        }
    }
    __syncthreads();

    float* sH = reinterpret_cast<float*>(sm);
    #pragma unroll
    for (int mi = 0; mi < 2; mi++) {
        const int row = wm * 32 + mi * 16 + r;
        const float bb0 = b1[row];
        const float bb1 = b1[row + 8];
        #pragma unroll
        for (int ni = 0; ni < 6; ni++) {
            const int px = prow * 96 + px0 + ni * 8 + 2 * q;
            sH[row * 194 + px]           = tanhf(d[mi][ni][0] + bb0);
            sH[row * 194 + px + 1]       = tanhf(d[mi][ni][1] + bb0);
            sH[(row + 8) * 194 + px]     = tanhf(d[mi][ni][2] + bb1);
            sH[(row + 8) * 194 + px + 1] = tanhf(d[mi][ni][3] + bb1);
        }
    }
    __syncthreads();

    float* sW2 = reinterpret_cast<float*>(sm) + 24832;
    float* sBv = reinterpret_cast<float*>(sm) + 29440;
    float* sBB = reinterpret_cast<float*>(sm) + 36544;
    #pragma unroll
    for (int itr = 0; itr < 9; itr++) {
        int i = tid + itr * 512;
        int ci = i / 36;
        int ch = i - ci * 36;
        sW2[i] = w2[ch * 128 + ci];
    }
    if (tid < 54) sBB[tid] = bbuf[tid];
    __syncthreads();

    if (tid < 384) {
        const int px  = tid >> 1;
        const int ch0 = (tid & 1) * 18;
        float a2c[18];
        #pragma unroll
        for (int qq = 0; qq < 18; qq++) a2c[qq] = 0.f;
        for (int ci = 0; ci < 128; ci++) {
            const float hv = sH[ci * 194 + px];
            const float* wr = &sW2[ci * 36 + ch0];
            #pragma unroll
            for (int qq = 0; qq < 18; qq++)
                a2c[qq] = fmaf(wr[qq], hv, a2c[qq]);
        }
        #pragma unroll
        for (int qq = 0; qq < 18; qq++)
            sBv[px * 37 + ch0 + qq] = tanhf(a2c[qq] + b2[ch0 + qq]);
    }
    __syncthreads();

    for (int i = tid; i < 54 * 192; i += 512) {
        const int j  = i / 192;
        const int px = i - j * 192;
        const int row = px / 96;
        const int x   = px - row * 96;
        const int m  = j / 9;
        const int l  = j - m * 9;
        float s = 0.f;
        #pragma unroll
        for (int t = 0; t < 6; t++)
            s = fmaf(sBv[px * 37 + m * 6 + t], sBB[t * 9 + l], s);
        g_bases[(n * 54 + j) * HW + (y0 + row) * W + x] = s;
    }
}

// ===========================================================================
// V-GEMM v5: 2-chunk K pipeline with ROLLED chunk loop (single compute body,
// no register duplication). PAD2 = 36 (conflict-free fragment LDS).
// ===========================================================================
constexpr int PAD2 = 36;
constexpr int VCH  = 128 * PAD2;            // 4608 u32
constexpr int VCHUNK = 4 * VCH;             // AHI, ALO, BHI, BLO
constexpr int VG_SMEM = 2 * VCHUNK * 4;     // 147456 B

__global__ __launch_bounds__(512, 1) void k_vgemm_mma()
{
    extern __shared__ u32 vsm[];
    const int tid = threadIdx.x;
    const int n  = blockIdx.z;
    const int r0 = blockIdx.y * 128;
    const int p0 = blockIdx.x * 128;

    auto stage = [&](int c) {
        u32* sAhi = vsm + c * VCHUNK;
        u32* sAlo = sAhi + VCH;
        u32* sBhi = sAlo + VCH;
        u32* sBlo = sBhi + VCH;
        #pragma unroll
        for (int it = 0; it < 2; it++) {
            int i = tid + it * 512;
            int m  = i >> 3;
            int k4 = i & 7;
            cp16(smem_u32p(&sAhi[m * PAD2 + k4 * 4]),
                 &g_ahi[(r0 + m) * 64 + c * 32 + k4 * 4]);
            cp16(smem_u32p(&sAlo[m * PAD2 + k4 * 4]),
                 &g_alo[(r0 + m) * 64 + c * 32 + k4 * 4]);
        }
        #pragma unroll
        for (int it = 0; it < 8; it++) {
            int idx = tid + it * 512;
            int k2l = idx >> 7;
            int p   = idx & 127;
            int gp  = p0 + p;
            int row = gp / 96;
            int col = gp - row * 96;
            int src = ((n * IN_CI + c * 32 + k2l) * IN_R + row + 1) * IN_CSTR + col + 1;
            cp4(smem_u32p(&sBhi[p * PAD2 + k2l]), &g_inhi[src]);
            cp4(smem_u32p(&sBlo[p * PAD2 + k2l]), &g_inlo[src]);
        }
    };

    const int wid = tid >> 5;
    const int lane = tid & 31;
    const int wm = wid & 3;
    const int wn = wid >> 2;
    const int r  = lane >> 2;
    const int q  = lane & 3;

    float d[2][4][4];
    #pragma unroll
    for (int mi = 0; mi < 2; mi++)
        #pragma unroll
        for (int ni = 0; ni < 4; ni++)
            #pragma unroll
            for (int e = 0; e < 4; e++) d[mi][ni][e] = 0.f;

    stage(0);
    cp_commit();
    stage(1);
    cp_commit();

    #pragma unroll 1
    for (int c = 0; c < 2; c++) {
        if (c == 0) cp_wait<1>(); else cp_wait<0>();
        __syncthreads();
        const u32* sAhi = vsm + c * VCHUNK;
        const u32* sAlo = sAhi + VCH;
        const u32* sBhi = sAlo + VCH;
        const u32* sBlo = sBhi + VCH;
        #pragma unroll
        for (int ks = 0; ks < 4; ks++) {
            const int kc = ks * 8;
            u32 ahi[2][4], alo[2][4];
            #pragma unroll
            for (int mi = 0; mi < 2; mi++) {
                const int ra = wm * 32 + mi * 16 + r;
                ahi[mi][0] = sAhi[ra * PAD2 + kc + q];
                ahi[mi][1] = sAhi[(ra + 8) * PAD2 + kc + q];
                ahi[mi][2] = sAhi[ra * PAD2 + kc + 4 + q];
                ahi[mi][3] = sAhi[(ra + 8) * PAD2 + kc + 4 + q];
                alo[mi][0] = sAlo[ra * PAD2 + kc + q];
                alo[mi][1] = sAlo[(ra + 8) * PAD2 + kc + q];
                alo[mi][2] = sAlo[ra * PAD2 + kc + 4 + q];
                alo[mi][3] = sAlo[(ra + 8) * PAD2 + kc + 4 + q];
            }
            #pragma unroll
            for (int ni = 0; ni < 4; ni++) {
                const int nb = wn * 32 + ni * 8 + r;
                u32 bhi0 = sBhi[nb * PAD2 + kc + q];
                u32 bhi1 = sBhi[nb * PAD2 + kc + 4 + q];
                u32 blo0 = sBlo[nb * PAD2 + kc + q];
                u32 blo1 = sBlo[nb * PAD2 + kc + 4 + q];
                #pragma unroll
                for (int mi = 0; mi < 2; mi++) {
                    mma_bf16(d[mi][ni], ahi[mi], bhi0, bhi1);
                    mma_bf16(d[mi][ni], ahi[mi], blo0, blo1);
                    mma_bf16(d[mi][ni], alo[mi], bhi0, bhi1);
                }
            }
        }
    }

    float* Vn = g_v + (size_t)n * K768 * HW;
    #pragma unroll
    for (int mi = 0; mi < 2; mi++) {
        const int row = r0 + wm * 32 + mi * 16 + r;
        #pragma unroll
        for (int ni = 0; ni < 4; ni++) {
            const int col = p0 + wn * 32 + ni * 8 + 2 * q;
            *reinterpret_cast<float2*>(&Vn[(size_t)row * HW + col]) =
                make_float2(d[mi][ni][0], d[mi][ni][1]);
            *reinterpret_cast<float2*>(&Vn[(size_t)(row + 8) * HW + col]) =
                make_float2(d[mi][ni][2], d[mi][ni][3]);
        }
    }
}

// ===========================================================================
// combine v3: 8 channels per block (grid.y = 16), m-outer loop.
// ===========================================================================
__global__ __launch_bounds__(256) void k_combine(
    const float* __restrict__ bias, float* __restrict__ out)
{
    const int p  = blockIdx.x * 256 + threadIdx.x;
    const int cb = blockIdx.y * 8;
    const int n  = p / HW;
    const int hw = p - n * HW;
    const int y  = hw / W;
    const int x  = hw - y * W;

    int  off[9];
    u32  okm = 0;
    #pragma unroll
    for (int l = 0; l < 9; l++) {
        const int dy = l / 3 - 1, dx = l % 3 - 1;
        const bool ok = (unsigned)(y + dy) < (unsigned)H && (unsigned)(x + dx) < (unsigned)W;
        off[l] = ok ? (dy * W + dx) : 0;
        okm |= (ok ? 1u : 0u) << l;
    }

    float acc[8];
    #pragma unroll
    for (int ci = 0; ci < 8; ci++) acc[ci] = 0.f;

    const float* Vn = g_v + (size_t)n * K768 * HW + hw;

    #pragma unroll
    for (int m = 0; m < 6; m++) {
        float bs[9];
        #pragma unroll
        for (int l = 0; l < 9; l++) {
            float t = __ldg(&g_bases[(n * 54 + m * 9 + l) * HW + hw]);
            bs[l] = (okm >> l & 1u) ? t : 0.f;
        }
        const float* Vm = Vn + (size_t)(cb * 6 + m) * HW;
        #pragma unroll
        for (int ci = 0; ci < 8; ci++) {
            const float* row = Vm + (size_t)(ci * 6) * HW;
            float s = 0.f;
            #pragma unroll
            for (int l = 0; l < 9; l++)
                s = fmaf(bs[l], __ldg(row + off[l]), s);
            acc[ci] += s;
        }
    }

    float* on = out + (size_t)n * C * HW + hw;
    #pragma unroll
    for (int ci = 0; ci < 8; ci++)
        on[(size_t)(cb + ci) * HW] = acc[ci] + __ldg(&bias[cb + ci]);
}

// ---------------------------------------------------------------------------
extern "C" void kernel_launch(void* const* d_in, const int* in_sizes, int n_in,
                              void* d_out, int out_size)
{
    const float* feat = (const float*)d_in[0];
    const float* wgt  = (const float*)d_in[1];
    const float* w1   = (const float*)d_in[2];
    const float* b1   = (const float*)d_in[3];
    const float* w2   = (const float*)d_in[4];
    const float* b2   = (const float*)d_in[5];
    const float* bbuf = (const float*)d_in[6];
    const float* coef = (const float*)d_in[7];
    const float* bias = (const float*)d_in[8];
    float* out = (float*)d_out;

    static bool attr_set = false;
    if (!attr_set) {
        cudaFuncSetAttribute(k_conv1_mma,
                             cudaFuncAttributeMaxDynamicSharedMemorySize, SM_BYTES);
        cudaFuncSetAttribute(k_vgemm_mma,
                             cudaFuncAttributeMaxDynamicSharedMemorySize, VG_SMEM);
        attr_set = true;
    }

    k_prep_in<<<(N * IN_NSTR) / 512, 512>>>(feat, wgt);
    k_prep_w1<<<(9 * 96 * 128) / 512, 512>>>(w1);
    k_prep_a<<<(K768 * 64) / 256, 256>>>(coef);

    dim3 g1(1, H / 2, N);
    k_conv1_mma<<<g1, 512, SM_BYTES>>>(b1, w2, b2, bbuf);

    dim3 g3(HW / 128, K768 / 128, N);
    k_vgemm_mma<<<g3, 512, VG_SMEM>>>();

    dim3 g4((N * HW) / 256, 16);
    k_combine<<<g4, 256>>>(bias, out);
}

// round 14
// speedup vs baseline: 1.2626x; 1.2492x over previous
#include <cuda_runtime.h>
#include <cuda_bf16.h>
#include <math.h>

typedef unsigned long long u64;
typedef unsigned int u32;

__device__ __forceinline__ unsigned smem_u32p(const void* p) {
    unsigned a;
    asm("{ .reg .u64 t; cvta.to.shared.u64 t, %1; cvt.u32.u64 %0, t; }" : "=r"(a) : "l"(p));
    return a;
}
__device__ __forceinline__ void cp16(unsigned dst, const void* src) {
    asm volatile("cp.async.cg.shared.global [%0], [%1], 16;" :: "r"(dst), "l"(src));
}
__device__ __forceinline__ void cp4(unsigned dst, const void* src) {
    asm volatile("cp.async.ca.shared.global [%0], [%1], 4;" :: "r"(dst), "l"(src));
}
__device__ __forceinline__ void cp_commit() { asm volatile("cp.async.commit_group;"); }
template <int Nw>
__device__ __forceinline__ void cp_wait() { asm volatile("cp.async.wait_group %0;" :: "n"(Nw)); }

// Problem constants
constexpr int N   = 8;
constexpr int C   = 128;
constexpr int CW  = 64;
constexpr int CIN = C + CW;   // 192
constexpr int H   = 96;
constexpr int W   = 96;
constexpr int HW  = H * W;    // 9216
constexpr int K768 = C * 6;   // 768

// Static scratch
__device__ float g_bases[N * 54 * HW];
__device__ float g_v    [(size_t)N * K768 * HW];
__device__ __align__(16) u32 g_ahi [K768 * 64];
__device__ __align__(16) u32 g_alo [K768 * 64];
__device__ __align__(16) u32 g_w1hi[9 * 96 * 128];
__device__ __align__(16) u32 g_w1lo[9 * 96 * 128];
// pre-split, pre-padded inputs: [n][96 ci2][98 rows][104 cols]
constexpr int IN_CI = 96;
constexpr int IN_R  = 98;
constexpr int IN_CSTR = 104;
constexpr int IN_NSTR = IN_CI * IN_R * IN_CSTR;
__device__ __align__(16) u32 g_inhi[N * IN_NSTR];
__device__ __align__(16) u32 g_inlo[N * IN_NSTR];

// ===========================================================================
__device__ __forceinline__ void split2(float f0, float f1, u32& hi, u32& lo) {
    __nv_bfloat16 h0 = __float2bfloat16_rn(f0);
    __nv_bfloat16 h1 = __float2bfloat16_rn(f1);
    float l0f = f0 - __bfloat162float(h0);
    float l1f = f1 - __bfloat162float(h1);
    __nv_bfloat16 l0 = __float2bfloat16_rn(l0f);
    __nv_bfloat16 l1 = __float2bfloat16_rn(l1f);
    hi = ((u32)__bfloat16_as_ushort(h1) << 16) | (u32)__bfloat16_as_ushort(h0);
    lo = ((u32)__bfloat16_as_ushort(l1) << 16) | (u32)__bfloat16_as_ushort(l0);
}

__device__ __forceinline__ void mma_bf16(float d[4], const u32 a[4], u32 b0, u32 b1) {
    asm volatile(
        "mma.sync.aligned.m16n8k16.row.col.f32.bf16.bf16.f32 "
        "{%0,%1,%2,%3}, {%4,%5,%6,%7}, {%8,%9}, {%0,%1,%2,%3};"
        : "+f"(d[0]), "+f"(d[1]), "+f"(d[2]), "+f"(d[3])
        : "r"(a[0]), "r"(a[1]), "r"(a[2]), "r"(a[3]), "r"(b0), "r"(b1));
}

// ===========================================================================
// prep kernels
// ===========================================================================
__global__ __launch_bounds__(256) void k_prep_a(const float* __restrict__ coef)
{
    const int idx = blockIdx.x * 256 + threadIdx.x;
    const int rg = idx >> 6;
    const int k2 = idx & 63;
    const int c  = rg / 6;
    const int mm = rg - c * 6;
    const int k  = 2 * k2;
    u32 hi, lo;
    split2(coef[c * K768 + k * 6 + mm], coef[c * K768 + (k + 1) * 6 + mm], hi, lo);
    g_ahi[idx] = hi;
    g_alo[idx] = lo;
}

__global__ __launch_bounds__(512) void k_prep_w1(const float* __restrict__ w1)
{
    const int idx = blockIdx.x * 512 + threadIdx.x;
    const int tap = idx / (96 * 128);
    const int rem = idx - tap * 96 * 128;
    const int ci2 = rem >> 7;
    const int co  = rem & 127;
    const float f0 = w1[(co * CIN + 2 * ci2)     * 9 + tap];
    const float f1 = w1[(co * CIN + 2 * ci2 + 1) * 9 + tap];
    u32 hi, lo;
    split2(f0, f1, hi, lo);
    g_w1hi[idx] = hi;
    g_w1lo[idx] = lo;
}

__global__ __launch_bounds__(512) void k_prep_in(
    const float* __restrict__ feat, const float* __restrict__ wgt)
{
    const int idx = blockIdx.x * 512 + threadIdx.x;
    const int n   = idx / IN_NSTR;
    int rem = idx - n * IN_NSTR;
    const int ci2 = rem / (IN_R * IN_CSTR);
    rem -= ci2 * (IN_R * IN_CSTR);
    const int row = rem / IN_CSTR;
    const int col = rem - row * IN_CSTR;
    float f0 = 0.f, f1 = 0.f;
    if (row >= 1 && row <= 96 && col >= 1 && col <= 96) {
        const int y = row - 1, x = col - 1;
        const float* b = (ci2 < 64)
            ? &feat[((n * C + 2 * ci2) * H + y) * W + x]
            : &wgt [((n * CW + 2 * (ci2 - 64)) * H + y) * W + x];
        f0 = b[0];
        f1 = b[HW];
    }
    u32 hi, lo;
    split2(f0, f1, hi, lo);
    g_inhi[idx] = hi;
    g_inlo[idx] = lo;
}

// ===========================================================================
// conv1 mma (R11 known-good, unchanged)
// ===========================================================================
constexpr int CISTR = 424;
constexpr int IHALF = 24 * CISTR;
constexpr int IBSZ  = 2 * IHALF;
constexpr int AB    = 2 * IBSZ;
constexpr int ASTR  = 136;
constexpr int ATILE = 24 * ASTR;
constexpr int SM_U32  = AB + 4 * ATILE;
constexpr int SM_BYTES = SM_U32 * 4;       // 215040 B

__global__ __launch_bounds__(512, 1) void k_conv1_mma(
    const float* __restrict__ b1,
    const float* __restrict__ w2,   const float* __restrict__ b2,
    const float* __restrict__ bbuf)
{
    extern __shared__ u32 sm[];
    const int tid  = threadIdx.x;
    const int wid  = tid >> 5;
    const int lane = tid & 31;
    const int wm = wid & 3;
    const int wn = wid >> 2;
    const int r  = lane >> 2;
    const int q  = lane & 3;

    const int n  = blockIdx.z;
    const int y0 = blockIdx.y * 2;

    float d[2][6][4];
    #pragma unroll
    for (int mi = 0; mi < 2; mi++)
        #pragma unroll
        for (int ni = 0; ni < 6; ni++)
            #pragma unroll
            for (int e = 0; e < 4; e++) d[mi][ni][e] = 0.f;

    auto stageA = [&](int tap, int cg, int buf) {
        const u32* srcH = g_w1hi + (tap * 96 + cg * 24) * 128;
        const u32* srcL = g_w1lo + (tap * 96 + cg * 24) * 128;
        u32* dH = sm + AB + buf * 2 * ATILE;
        u32* dL = dH + ATILE;
        #pragma unroll
        for (int it = 0; it < 2; it++) {
            int i = tid + it * 512;
            if (i < 768) {
                int ci2l = i >> 5;
                int c4   = (i & 31) * 4;
                cp16(smem_u32p(&dH[ci2l * ASTR + c4]), &srcH[ci2l * 128 + c4]);
                cp16(smem_u32p(&dL[ci2l * ASTR + c4]), &srcL[ci2l * 128 + c4]);
            }
        }
    };

    auto stageInRange = [&](int cgT, int buf, int c0, int c1) {
        const int ibase = buf * IBSZ;
        const int cnt = (c1 - c0) * 200;
        for (int i = tid; i < cnt; i += 512) {
            int ci2o = i / 200;
            int rem  = i - ci2o * 200;
            int arr  = rem / 100;
            int rem2 = rem - arr * 100;
            int rr   = rem2 / 25;
            int f4   = rem2 - rr * 25;
            int dst  = ibase + arr * IHALF + (c0 + ci2o) * CISTR + rr * 100 + f4 * 4;
            int src  = ((n * IN_CI + cgT * 24 + c0 + ci2o) * IN_R + y0 + rr) * IN_CSTR + f4 * 4;
            cp16(smem_u32p(&sm[dst]), arr ? &g_inlo[src] : &g_inhi[src]);
        }
    };

    stageInRange(0, 0, 0, 24);
    stageA(0, 0, 0);
    cp_commit();

    const int prow = wn >> 1;
    const int px0  = (wn & 1) * 48;

    int it = 0;
    for (int cg = 0; cg < 4; cg++) {
        const int ib = (cg & 1) * IBSZ;
        for (int tap = 0; tap < 9; tap++, it++) {
            const int abuf = it & 1;
            __syncthreads();
            if (tap >= 2 && tap <= 5 && cg < 3)
                stageInRange(cg + 1, (cg + 1) & 1, (tap - 2) * 6, (tap - 1) * 6);
            if (it + 1 < 36) {
                stageA((it + 1) % 9, (it + 1) / 9, abuf ^ 1);
                cp_commit();
                cp_wait<1>();
            } else {
                cp_wait<0>();
            }
            __syncthreads();

            const int ky = tap / 3, kx = tap % 3;
            const u32* AH = sm + AB + abuf * 2 * ATILE;
            const u32* AL = AH + ATILE;
            const int boff = (prow + ky) * 100 + kx + px0;

            #pragma unroll
            for (int s = 0; s < 3; s++) {
                const int kb2 = s * 8;
                u32 ahi[2][4], alo[2][4];
                #pragma unroll
                for (int mi = 0; mi < 2; mi++) {
                    const int ra = wm * 32 + mi * 16 + r;
                    ahi[mi][0] = AH[(kb2 + q) * ASTR + ra];
                    ahi[mi][1] = AH[(kb2 + q) * ASTR + ra + 8];
                    ahi[mi][2] = AH[(kb2 + 4 + q) * ASTR + ra];
                    ahi[mi][3] = AH[(kb2 + 4 + q) * ASTR + ra + 8];
                    alo[mi][0] = AL[(kb2 + q) * ASTR + ra];
                    alo[mi][1] = AL[(kb2 + q) * ASTR + ra + 8];
                    alo[mi][2] = AL[(kb2 + 4 + q) * ASTR + ra];
                    alo[mi][3] = AL[(kb2 + 4 + q) * ASTR + ra + 8];
                }
                #pragma unroll
                for (int ni = 0; ni < 6; ni++) {
                    const int a0 = (kb2 + q) * CISTR + boff + ni * 8 + r;
                    const int a1 = (kb2 + 4 + q) * CISTR + boff + ni * 8 + r;
                    const u32 bhi0 = sm[ib + a0];
                    const u32 bhi1 = sm[ib + a1];
                    const u32 blo0 = sm[ib + IHALF + a0];
                    const u32 blo1 = sm[ib + IHALF + a1];
                    #pragma unroll
                    for (int mi = 0; mi < 2; mi++) {
                        mma_bf16(d[mi][ni], ahi[mi], bhi0, bhi1);
                        mma_bf16(d[mi][ni], ahi[mi], blo0, blo1);
                        mma_bf16(d[mi][ni], alo[mi], bhi0, bhi1);
                    }
                }
            }
        }
    }
    __syncthreads();

    float* sH = reinterpret_cast<float*>(sm);
    #pragma unroll
    for (int mi = 0; mi < 2; mi++) {
        const int row = wm * 32 + mi * 16 + r;
        const float bb0 = b1[row];
        const float bb1 = b1[row + 8];
        #pragma unroll
        for (int ni = 0; ni < 6; ni++) {
            const int px = prow * 96 + px0 + ni * 8 + 2 * q;
            sH[row * 194 + px]           = tanhf(d[mi][ni][0] + bb0);
            sH[row * 194 + px + 1]       = tanhf(d[mi][ni][1] + bb0);
            sH[(row + 8) * 194 + px]     = tanhf(d[mi][ni][2] + bb1);
            sH[(row + 8) * 194 + px + 1] = tanhf(d[mi][ni][3] + bb1);
        }
    }
    __syncthreads();

    float* sW2 = reinterpret_cast<float*>(sm) + 24832;
    float* sBv = reinterpret_cast<float*>(sm) + 29440;
    float* sBB = reinterpret_cast<float*>(sm) + 36544;
    #pragma unroll
    for (int itr = 0; itr < 9; itr++) {
        int i = tid + itr * 512;
        int ci = i / 36;
        int ch = i - ci * 36;
        sW2[i] = w2[ch * 128 + ci];
    }
    if (tid < 54) sBB[tid] = bbuf[tid];
    __syncthreads();

    if (tid < 384) {
        const int px  = tid >> 1;
        const int ch0 = (tid & 1) * 18;
        float a2c[18];
        #pragma unroll
        for (int qq = 0; qq < 18; qq++) a2c[qq] = 0.f;
        for (int ci = 0; ci < 128; ci++) {
            const float hv = sH[ci * 194 + px];
            const float* wr = &sW2[ci * 36 + ch0];
            #pragma unroll
            for (int qq = 0; qq < 18; qq++)
                a2c[qq] = fmaf(wr[qq], hv, a2c[qq]);
        }
        #pragma unroll
        for (int qq = 0; qq < 18; qq++)
            sBv[px * 37 + ch0 + qq] = tanhf(a2c[qq] + b2[ch0 + qq]);
    }
    __syncthreads();

    for (int i = tid; i < 54 * 192; i += 512) {
        const int j  = i / 192;
        const int px = i - j * 192;
        const int row = px / 96;
        const int x   = px - row * 96;
        const int m  = j / 9;
        const int l  = j - m * 9;
        float s = 0.f;
        #pragma unroll
        for (int t = 0; t < 6; t++)
            s = fmaf(sBv[px * 37 + m * 6 + t], sBB[t * 9 + l], s);
        g_bases[(n * 54 + j) * HW + (y0 + row) * W + x] = s;
    }
}

// ===========================================================================
// V-GEMM (exact R11 known-good: PAD 68, single-stage cp.async)
// ===========================================================================
constexpr int PAD = 68;
constexpr int VG_SMEM = 4 * 128 * PAD * 4;

__global__ __launch_bounds__(512, 1) void k_vgemm_mma()
{
    extern __shared__ u32 vsm[];
    u32* sAhi = vsm;
    u32* sAlo = vsm + 128 * PAD;
    u32* sBhi = vsm + 2 * 128 * PAD;
    u32* sBlo = vsm + 3 * 128 * PAD;

    const int tid = threadIdx.x;
    const int n  = blockIdx.z;
    const int r0 = blockIdx.y * 128;
    const int p0 = blockIdx.x * 128;

    #pragma unroll
    for (int it = 0; it < 4; it++) {
        int i = tid + it * 512;
        int m  = i >> 4;
        int k4 = i & 15;
        cp16(smem_u32p(&sAhi[m * PAD + k4 * 4]), &g_ahi[(r0 + m) * 64 + k4 * 4]);
        cp16(smem_u32p(&sAlo[m * PAD + k4 * 4]), &g_alo[(r0 + m) * 64 + k4 * 4]);
    }
    #pragma unroll
    for (int it = 0; it < 16; it++) {
        int idx = tid + it * 512;
        int k2 = idx >> 7;
        int p  = idx & 127;
        int gp = p0 + p;
        int row = gp / 96;
        int col = gp - row * 96;
        int src = ((n * IN_CI + k2) * IN_R + row + 1) * IN_CSTR + col + 1;
        cp4(smem_u32p(&sBhi[p * PAD + k2]), &g_inhi[src]);
        cp4(smem_u32p(&sBlo[p * PAD + k2]), &g_inlo[src]);
    }
    cp_commit();
    cp_wait<0>();
    __syncthreads();

    const int wid = tid >> 5;
    const int lane = tid & 31;
    const int wm = wid & 3;
    const int wn = wid >> 2;
    const int r  = lane >> 2;
    const int q  = lane & 3;

    float d[2][4][4];
    #pragma unroll
    for (int mi = 0; mi < 2; mi++)
        #pragma unroll
        for (int ni = 0; ni < 4; ni++)
            #pragma unroll
            for (int e = 0; e < 4; e++) d[mi][ni][e] = 0.f;

    #pragma unroll
    for (int ks = 0; ks < 8; ks++) {
        const int kc = ks * 8;
        u32 ahi[2][4], alo[2][4];
        #pragma unroll
        for (int mi = 0; mi < 2; mi++) {
            const int ra = wm * 32 + mi * 16 + r;
            ahi[mi][0] = sAhi[ra * PAD + kc + q];
            ahi[mi][1] = sAhi[(ra + 8) * PAD + kc + q];
            ahi[mi][2] = sAhi[ra * PAD + kc + 4 + q];
            ahi[mi][3] = sAhi[(ra + 8) * PAD + kc + 4 + q];
            alo[mi][0] = sAlo[ra * PAD + kc + q];
            alo[mi][1] = sAlo[(ra + 8) * PAD + kc + q];
            alo[mi][2] = sAlo[ra * PAD + kc + 4 + q];
            alo[mi][3] = sAlo[(ra + 8) * PAD + kc + 4 + q];
        }
        #pragma unroll
        for (int ni = 0; ni < 4; ni++) {
            const int nb = wn * 32 + ni * 8 + r;
            u32 bhi0 = sBhi[nb * PAD + kc + q];
            u32 bhi1 = sBhi[nb * PAD + kc + 4 + q];
            u32 blo0 = sBlo[nb * PAD + kc + q];
            u32 blo1 = sBlo[nb * PAD + kc + 4 + q];
            #pragma unroll
            for (int mi = 0; mi < 2; mi++) {
                mma_bf16(d[mi][ni], ahi[mi], bhi0, bhi1);
                mma_bf16(d[mi][ni], ahi[mi], blo0, blo1);
                mma_bf16(d[mi][ni], alo[mi], bhi0, bhi1);
            }
        }
    }

    float* Vn = g_v + (size_t)n * K768 * HW;
    #pragma unroll
    for (int mi = 0; mi < 2; mi++) {
        const int row = r0 + wm * 32 + mi * 16 + r;
        #pragma unroll
        for (int ni = 0; ni < 4; ni++) {
            const int col = p0 + wn * 32 + ni * 8 + 2 * q;
            *reinterpret_cast<float2*>(&Vn[(size_t)row * HW + col]) =
                make_float2(d[mi][ni][0], d[mi][ni][1]);
            *reinterpret_cast<float2*>(&Vn[(size_t)(row + 8) * HW + col]) =
                make_float2(d[mi][ni][2], d[mi][ni][3]);
        }
    }
}

// ===========================================================================
// combine v4: pixel-pair. Each thread handles pixels (hw, hw+1), 8 channels.
// Shared V loads across the pair: 12 loads per (m,ci) instead of 18.
// ===========================================================================
__global__ __launch_bounds__(256) void k_combine(
    const float* __restrict__ bias, float* __restrict__ out)
{
    const int idx = blockIdx.x * 256 + threadIdx.x;    // [0, N*HW/2)
    const int cb  = blockIdx.y * 8;
    const int n   = idx / (HW / 2);
    const int hw  = (idx - n * (HW / 2)) * 2;
    const int y   = hw / W;
    const int x   = hw - y * W;                         // x even

    // row offsets + validity
    int  rowoff[3];
    bool rok[3];
    #pragma unroll
    for (int dyi = 0; dyi < 3; dyi++) {
        const int dy = dyi - 1;
        rok[dyi] = (unsigned)(y + dy) < (unsigned)H;
        rowoff[dyi] = rok[dyi] ? dy * W : 0;
    }
    // clamped column offsets for cols x-1 .. x+2 (relative to x)
    const bool c0ok = (x > 0);
    const bool c3ok = (x + 2 < W);
    int coladd[4];
    coladd[0] = c0ok ? -1 : 0;
    coladd[1] = 0;
    coladd[2] = 1;
    coladd[3] = c3ok ? 2 : 1;

    float acc0[8], acc1[8];
    #pragma unroll
    for (int ci = 0; ci < 8; ci++) { acc0[ci] = 0.f; acc1[ci] = 0.f; }

    const float* Vn = g_v + (size_t)n * K768 * HW + hw;

    #pragma unroll
    for (int m = 0; m < 6; m++) {
        float bs0[9], bs1[9];
        #pragma unroll
        for (int l = 0; l < 9; l++) {
            const int dyi = l / 3, kx = l % 3;
            const float* bp = &g_bases[(n * 54 + m * 9 + l) * HW + hw];
            float t0 = __ldg(bp);
            float t1 = __ldg(bp + 1);
            // px0 uses col x-1+kx (invalid only kx==0 && !c0ok)
            bool v0 = rok[dyi] && (kx > 0 || c0ok);
            // px1 uses col x+kx (invalid only kx==2 && !c3ok)
            bool v1 = rok[dyi] && (kx < 2 || c3ok);
            bs0[l] = v0 ? t0 : 0.f;
            bs1[l] = v1 ? t1 : 0.f;
        }
        const float* Vm = Vn + (size_t)(cb * 6 + m) * HW;
        #pragma unroll
        for (int ci = 0; ci < 8; ci++) {
            const float* row = Vm + (size_t)(ci * 6) * HW;
            float s0 = 0.f, s1 = 0.f;
            #pragma unroll
            for (int dyi = 0; dyi < 3; dyi++) {
                const float* rp = row + rowoff[dyi];
                float v0 = __ldg(rp + coladd[0]);
                float v1 = __ldg(rp + coladd[1]);
                float v2 = __ldg(rp + coladd[2]);
                float v3 = __ldg(rp + coladd[3]);
                s0 = fmaf(bs0[dyi * 3 + 0], v0, s0);
                s0 = fmaf(bs0[dyi * 3 + 1], v1, s0);
                s0 = fmaf(bs0[dyi * 3 + 2], v2, s0);
                s1 = fmaf(bs1[dyi * 3 + 0], v1, s1);
                s1 = fmaf(bs1[dyi * 3 + 1], v2, s1);
                s1 = fmaf(bs1[dyi * 3 + 2], v3, s1);
            }
            acc0[ci] += s0;
            acc1[ci] += s1;
        }
    }

    float* on = out + (size_t)n * C * HW + hw;
    #pragma unroll
    for (int ci = 0; ci < 8; ci++) {
        const float bb = __ldg(&bias[cb + ci]);
        *reinterpret_cast<float2*>(&on[(size_t)(cb + ci) * HW]) =
            make_float2(acc0[ci] + bb, acc1[ci] + bb);
    }
}

// ---------------------------------------------------------------------------
extern "C" void kernel_launch(void* const* d_in, const int* in_sizes, int n_in,
                              void* d_out, int out_size)
{
    const float* feat = (const float*)d_in[0];
    const float* wgt  = (const float*)d_in[1];
    const float* w1   = (const float*)d_in[2];
    const float* b1   = (const float*)d_in[3];
    const float* w2   = (const float*)d_in[4];
    const float* b2   = (const float*)d_in[5];
    const float* bbuf = (const float*)d_in[6];
    const float* coef = (const float*)d_in[7];
    const float* bias = (const float*)d_in[8];
    float* out = (float*)d_out;

    static bool attr_set = false;
    if (!attr_set) {
        cudaFuncSetAttribute(k_conv1_mma,
                             cudaFuncAttributeMaxDynamicSharedMemorySize, SM_BYTES);
        cudaFuncSetAttribute(k_vgemm_mma,
                             cudaFuncAttributeMaxDynamicSharedMemorySize, VG_SMEM);
        attr_set = true;
    }

    k_prep_in<<<(N * IN_NSTR) / 512, 512>>>(feat, wgt);
    k_prep_w1<<<(9 * 96 * 128) / 512, 512>>>(w1);
    k_prep_a<<<(K768 * 64) / 256, 256>>>(coef);

    dim3 g1(1, H / 2, N);
    k_conv1_mma<<<g1, 512, SM_BYTES>>>(b1, w2, b2, bbuf);

    dim3 g3(HW / 128, K768 / 128, N);
    k_vgemm_mma<<<g3, 512, VG_SMEM>>>();

    dim3 g4((N * HW / 2) / 256, 16);
    k_combine<<<g4, 256>>>(bias, out);
}

// round 15
// speedup vs baseline: 1.3893x; 1.1003x over previous
#include <cuda_runtime.h>
#include <cuda_bf16.h>
#include <math.h>

typedef unsigned long long u64;
typedef unsigned int u32;

__device__ __forceinline__ unsigned smem_u32p(const void* p) {
    unsigned a;
    asm("{ .reg .u64 t; cvta.to.shared.u64 t, %1; cvt.u32.u64 %0, t; }" : "=r"(a) : "l"(p));
    return a;
}
__device__ __forceinline__ void cp16(unsigned dst, const void* src) {
    asm volatile("cp.async.cg.shared.global [%0], [%1], 16;" :: "r"(dst), "l"(src));
}
__device__ __forceinline__ void cp4(unsigned dst, const void* src) {
    asm volatile("cp.async.ca.shared.global [%0], [%1], 4;" :: "r"(dst), "l"(src));
}
__device__ __forceinline__ void cp_commit() { asm volatile("cp.async.commit_group;"); }
template <int Nw>
__device__ __forceinline__ void cp_wait() { asm volatile("cp.async.wait_group %0;" :: "n"(Nw)); }

// Problem constants
constexpr int N   = 8;
constexpr int C   = 128;
constexpr int CW  = 64;
constexpr int CIN = C + CW;   // 192
constexpr int H   = 96;
constexpr int W   = 96;
constexpr int HW  = H * W;    // 9216
constexpr int K768 = C * 6;   // 768

// Static scratch
__device__ float g_bases[N * 54 * HW];
__device__ float g_v    [(size_t)N * K768 * HW];
__device__ __align__(16) u32 g_ahi [K768 * 64];
__device__ __align__(16) u32 g_alo [K768 * 64];
__device__ __align__(16) u32 g_w1hi[9 * 96 * 128];
__device__ __align__(16) u32 g_w1lo[9 * 96 * 128];
// pre-split, pre-padded inputs: [n][96 ci2][98 rows][104 cols]
constexpr int IN_CI = 96;
constexpr int IN_R  = 98;
constexpr int IN_CSTR = 104;
constexpr int IN_NSTR = IN_CI * IN_R * IN_CSTR;
__device__ __align__(16) u32 g_inhi[N * IN_NSTR];
__device__ __align__(16) u32 g_inlo[N * IN_NSTR];

// ===========================================================================
__device__ __forceinline__ void split2(float f0, float f1, u32& hi, u32& lo) {
    __nv_bfloat16 h0 = __float2bfloat16_rn(f0);
    __nv_bfloat16 h1 = __float2bfloat16_rn(f1);
    float l0f = f0 - __bfloat162float(h0);
    float l1f = f1 - __bfloat162float(h1);
    __nv_bfloat16 l0 = __float2bfloat16_rn(l0f);
    __nv_bfloat16 l1 = __float2bfloat16_rn(l1f);
    hi = ((u32)__bfloat16_as_ushort(h1) << 16) | (u32)__bfloat16_as_ushort(h0);
    lo = ((u32)__bfloat16_as_ushort(l1) << 16) | (u32)__bfloat16_as_ushort(l0);
}

__device__ __forceinline__ void mma_bf16(float d[4], const u32 a[4], u32 b0, u32 b1) {
    asm volatile(
        "mma.sync.aligned.m16n8k16.row.col.f32.bf16.bf16.f32 "
        "{%0,%1,%2,%3}, {%4,%5,%6,%7}, {%8,%9}, {%0,%1,%2,%3};"
        : "+f"(d[0]), "+f"(d[1]), "+f"(d[2]), "+f"(d[3])
        : "r"(a[0]), "r"(a[1]), "r"(a[2]), "r"(a[3]), "r"(b0), "r"(b1));
}

// ===========================================================================
// prep kernels
// ===========================================================================
__global__ __launch_bounds__(256) void k_prep_a(const float* __restrict__ coef)
{
    const int idx = blockIdx.x * 256 + threadIdx.x;
    const int rg = idx >> 6;
    const int k2 = idx & 63;
    const int c  = rg / 6;
    const int mm = rg - c * 6;
    const int k  = 2 * k2;
    u32 hi, lo;
    split2(coef[c * K768 + k * 6 + mm], coef[c * K768 + (k + 1) * 6 + mm], hi, lo);
    g_ahi[idx] = hi;
    g_alo[idx] = lo;
}

__global__ __launch_bounds__(512) void k_prep_w1(const float* __restrict__ w1)
{
    const int idx = blockIdx.x * 512 + threadIdx.x;
    const int tap = idx / (96 * 128);
    const int rem = idx - tap * 96 * 128;
    const int ci2 = rem >> 7;
    const int co  = rem & 127;
    const float f0 = w1[(co * CIN + 2 * ci2)     * 9 + tap];
    const float f1 = w1[(co * CIN + 2 * ci2 + 1) * 9 + tap];
    u32 hi, lo;
    split2(f0, f1, hi, lo);
    g_w1hi[idx] = hi;
    g_w1lo[idx] = lo;
}

__global__ __launch_bounds__(512) void k_prep_in(
    const float* __restrict__ feat, const float* __restrict__ wgt)
{
    const int idx = blockIdx.x * 512 + threadIdx.x;
    const int n   = idx / IN_NSTR;
    int rem = idx - n * IN_NSTR;
    const int ci2 = rem / (IN_R * IN_CSTR);
    rem -= ci2 * (IN_R * IN_CSTR);
    const int row = rem / IN_CSTR;
    const int col = rem - row * IN_CSTR;
    float f0 = 0.f, f1 = 0.f;
    if (row >= 1 && row <= 96 && col >= 1 && col <= 96) {
        const int y = row - 1, x = col - 1;
        const float* b = (ci2 < 64)
            ? &feat[((n * C + 2 * ci2) * H + y) * W + x]
            : &wgt [((n * CW + 2 * (ci2 - 64)) * H + y) * W + x];
        f0 = b[0];
        f1 = b[HW];
    }
    u32 hi, lo;
    split2(f0, f1, hi, lo);
    g_inhi[idx] = hi;
    g_inlo[idx] = lo;
}

// ===========================================================================
// conv1 mma: R11 structure with SINGLE barrier per tap-iteration.
// Safety: cp_wait<0> + one __syncthreads at iter i proves (a) A(i) visible,
// (b) all warps finished compute(i-1) -> staging A(i+1) into buf^1 is safe.
// ===========================================================================
constexpr int CISTR = 424;
constexpr int IHALF = 24 * CISTR;
constexpr int IBSZ  = 2 * IHALF;
constexpr int AB    = 2 * IBSZ;
constexpr int ASTR  = 136;
constexpr int ATILE = 24 * ASTR;
constexpr int SM_U32  = AB + 4 * ATILE;
constexpr int SM_BYTES = SM_U32 * 4;       // 215040 B

__global__ __launch_bounds__(512, 1) void k_conv1_mma(
    const float* __restrict__ b1,
    const float* __restrict__ w2,   const float* __restrict__ b2,
    const float* __restrict__ bbuf)
{
    extern __shared__ u32 sm[];
    const int tid  = threadIdx.x;
    const int wid  = tid >> 5;
    const int lane = tid & 31;
    const int wm = wid & 3;
    const int wn = wid >> 2;
    const int r  = lane >> 2;
    const int q  = lane & 3;

    const int n  = blockIdx.z;
    const int y0 = blockIdx.y * 2;

    float d[2][6][4];
    #pragma unroll
    for (int mi = 0; mi < 2; mi++)
        #pragma unroll
        for (int ni = 0; ni < 6; ni++)
            #pragma unroll
            for (int e = 0; e < 4; e++) d[mi][ni][e] = 0.f;

    auto stageA = [&](int tap, int cg, int buf) {
        const u32* srcH = g_w1hi + (tap * 96 + cg * 24) * 128;
        const u32* srcL = g_w1lo + (tap * 96 + cg * 24) * 128;
        u32* dH = sm + AB + buf * 2 * ATILE;
        u32* dL = dH + ATILE;
        #pragma unroll
        for (int it = 0; it < 2; it++) {
            int i = tid + it * 512;
            if (i < 768) {
                int ci2l = i >> 5;
                int c4   = (i & 31) * 4;
                cp16(smem_u32p(&dH[ci2l * ASTR + c4]), &srcH[ci2l * 128 + c4]);
                cp16(smem_u32p(&dL[ci2l * ASTR + c4]), &srcL[ci2l * 128 + c4]);
            }
        }
    };

    auto stageInRange = [&](int cgT, int buf, int c0, int c1) {
        const int ibase = buf * IBSZ;
        const int cnt = (c1 - c0) * 200;
        for (int i = tid; i < cnt; i += 512) {
            int ci2o = i / 200;
            int rem  = i - ci2o * 200;
            int arr  = rem / 100;
            int rem2 = rem - arr * 100;
            int rr   = rem2 / 25;
            int f4   = rem2 - rr * 25;
            int dst  = ibase + arr * IHALF + (c0 + ci2o) * CISTR + rr * 100 + f4 * 4;
            int src  = ((n * IN_CI + cgT * 24 + c0 + ci2o) * IN_R + y0 + rr) * IN_CSTR + f4 * 4;
            cp16(smem_u32p(&sm[dst]), arr ? &g_inlo[src] : &g_inhi[src]);
        }
    };

    stageInRange(0, 0, 0, 24);
    stageA(0, 0, 0);
    cp_commit();

    const int prow = wn >> 1;
    const int px0  = (wn & 1) * 48;

    int it = 0;
    for (int cg = 0; cg < 4; cg++) {
        const int ib = (cg & 1) * IBSZ;
        for (int tap = 0; tap < 9; tap++, it++) {
            const int abuf = it & 1;
            cp_wait<0>();        // own group with A(it) complete
            __syncthreads();     // A(it) visible; all warps past compute(it-1)
            if (tap >= 2 && tap <= 5 && cg < 3)
                stageInRange(cg + 1, (cg + 1) & 1, (tap - 2) * 6, (tap - 1) * 6);
            if (it + 1 < 36) {
                stageA((it + 1) % 9, (it + 1) / 9, abuf ^ 1);
                cp_commit();
            }

            const int ky = tap / 3, kx = tap % 3;
            const u32* AH = sm + AB + abuf * 2 * ATILE;
            const u32* AL = AH + ATILE;
            const int boff = (prow + ky) * 100 + kx + px0;

            #pragma unroll
            for (int s = 0; s < 3; s++) {
                const int kb2 = s * 8;
                u32 ahi[2][4], alo[2][4];
                #pragma unroll
                for (int mi = 0; mi < 2; mi++) {
                    const int ra = wm * 32 + mi * 16 + r;
                    ahi[mi][0] = AH[(kb2 + q) * ASTR + ra];
                    ahi[mi][1] = AH[(kb2 + q) * ASTR + ra + 8];
                    ahi[mi][2] = AH[(kb2 + 4 + q) * ASTR + ra];
                    ahi[mi][3] = AH[(kb2 + 4 + q) * ASTR + ra + 8];
                    alo[mi][0] = AL[(kb2 + q) * ASTR + ra];
                    alo[mi][1] = AL[(kb2 + q) * ASTR + ra + 8];
                    alo[mi][2] = AL[(kb2 + 4 + q) * ASTR + ra];
                    alo[mi][3] = AL[(kb2 + 4 + q) * ASTR + ra + 8];
                }
                #pragma unroll
                for (int ni = 0; ni < 6; ni++) {
                    const int a0 = (kb2 + q) * CISTR + boff + ni * 8 + r;
                    const int a1 = (kb2 + 4 + q) * CISTR + boff + ni * 8 + r;
                    const u32 bhi0 = sm[ib + a0];
                    const u32 bhi1 = sm[ib + a1];
                    const u32 blo0 = sm[ib + IHALF + a0];
                    const u32 blo1 = sm[ib + IHALF + a1];
                    #pragma unroll
                    for (int mi = 0; mi < 2; mi++) {
                        mma_bf16(d[mi][ni], ahi[mi], bhi0, bhi1);
                        mma_bf16(d[mi][ni], ahi[mi], blo0, blo1);
                        mma_bf16(d[mi][ni], alo[mi], bhi0, bhi1);
                    }
                }
            }
        }
    }
    __syncthreads();

    float* sH = reinterpret_cast<float*>(sm);
    #pragma unroll
    for (int mi = 0; mi < 2; mi++) {
        const int row = wm * 32 + mi * 16 + r;
        const float bb0 = b1[row];
        const float bb1 = b1[row + 8];
        #pragma unroll
        for (int ni = 0; ni < 6; ni++) {
            const int px = prow * 96 + px0 + ni * 8 + 2 * q;
            sH[row * 194 + px]           = tanhf(d[mi][ni][0] + bb0);
            sH[row * 194 + px + 1]       = tanhf(d[mi][ni][1] + bb0);
            sH[(row + 8) * 194 + px]     = tanhf(d[mi][ni][2] + bb1);
            sH[(row + 8) * 194 + px + 1] = tanhf(d[mi][ni][3] + bb1);
        }
    }
    __syncthreads();

    float* sW2 = reinterpret_cast<float*>(sm) + 24832;
    float* sBv = reinterpret_cast<float*>(sm) + 29440;
    float* sBB = reinterpret_cast<float*>(sm) + 36544;
    #pragma unroll
    for (int itr = 0; itr < 9; itr++) {
        int i = tid + itr * 512;
        int ci = i / 36;
        int ch = i - ci * 36;
        sW2[i] = w2[ch * 128 + ci];
    }
    if (tid < 54) sBB[tid] = bbuf[tid];
    __syncthreads();

    if (tid < 384) {
        const int px  = tid >> 1;
        const int ch0 = (tid & 1) * 18;
        float a2c[18];
        #pragma unroll
        for (int qq = 0; qq < 18; qq++) a2c[qq] = 0.f;
        for (int ci = 0; ci < 128; ci++) {
            const float hv = sH[ci * 194 + px];
            const float* wr = &sW2[ci * 36 + ch0];
            #pragma unroll
            for (int qq = 0; qq < 18; qq++)
                a2c[qq] = fmaf(wr[qq], hv, a2c[qq]);
        }
        #pragma unroll
        for (int qq = 0; qq < 18; qq++)
            sBv[px * 37 + ch0 + qq] = tanhf(a2c[qq] + b2[ch0 + qq]);
    }
    __syncthreads();

    for (int i = tid; i < 54 * 192; i += 512) {
        const int j  = i / 192;
        const int px = i - j * 192;
        const int row = px / 96;
        const int x   = px - row * 96;
        const int m  = j / 9;
        const int l  = j - m * 9;
        float s = 0.f;
        #pragma unroll
        for (int t = 0; t < 6; t++)
            s = fmaf(sBv[px * 37 + m * 6 + t], sBB[t * 9 + l], s);
        g_bases[(n * 54 + j) * HW + (y0 + row) * W + x] = s;
    }
}

// ===========================================================================
// V-GEMM (exact R11 known-good)
// ===========================================================================
constexpr int PAD = 68;
constexpr int VG_SMEM = 4 * 128 * PAD * 4;

__global__ __launch_bounds__(512, 1) void k_vgemm_mma()
{
    extern __shared__ u32 vsm[];
    u32* sAhi = vsm;
    u32* sAlo = vsm + 128 * PAD;
    u32* sBhi = vsm + 2 * 128 * PAD;
    u32* sBlo = vsm + 3 * 128 * PAD;

    const int tid = threadIdx.x;
    const int n  = blockIdx.z;
    const int r0 = blockIdx.y * 128;
    const int p0 = blockIdx.x * 128;

    #pragma unroll
    for (int it = 0; it < 4; it++) {
        int i = tid + it * 512;
        int m  = i >> 4;
        int k4 = i & 15;
        cp16(smem_u32p(&sAhi[m * PAD + k4 * 4]), &g_ahi[(r0 + m) * 64 + k4 * 4]);
        cp16(smem_u32p(&sAlo[m * PAD + k4 * 4]), &g_alo[(r0 + m) * 64 + k4 * 4]);
    }
    #pragma unroll
    for (int it = 0; it < 16; it++) {
        int idx = tid + it * 512;
        int k2 = idx >> 7;
        int p  = idx & 127;
        int gp = p0 + p;
        int row = gp / 96;
        int col = gp - row * 96;
        int src = ((n * IN_CI + k2) * IN_R + row + 1) * IN_CSTR + col + 1;
        cp4(smem_u32p(&sBhi[p * PAD + k2]), &g_inhi[src]);
        cp4(smem_u32p(&sBlo[p * PAD + k2]), &g_inlo[src]);
    }
    cp_commit();
    cp_wait<0>();
    __syncthreads();

    const int wid = tid >> 5;
    const int lane = tid & 31;
    const int wm = wid & 3;
    const int wn = wid >> 2;
    const int r  = lane >> 2;
    const int q  = lane & 3;

    float d[2][4][4];
    #pragma unroll
    for (int mi = 0; mi < 2; mi++)
        #pragma unroll
        for (int ni = 0; ni < 4; ni++)
            #pragma unroll
            for (int e = 0; e < 4; e++) d[mi][ni][e] = 0.f;

    #pragma unroll
    for (int ks = 0; ks < 8; ks++) {
        const int kc = ks * 8;
        u32 ahi[2][4], alo[2][4];
        #pragma unroll
        for (int mi = 0; mi < 2; mi++) {
            const int ra = wm * 32 + mi * 16 + r;
            ahi[mi][0] = sAhi[ra * PAD + kc + q];
            ahi[mi][1] = sAhi[(ra + 8) * PAD + kc + q];
            ahi[mi][2] = sAhi[ra * PAD + kc + 4 + q];
            ahi[mi][3] = sAhi[(ra + 8) * PAD + kc + 4 + q];
            alo[mi][0] = sAlo[ra * PAD + kc + q];
            alo[mi][1] = sAlo[(ra + 8) * PAD + kc + q];
            alo[mi][2] = sAlo[ra * PAD + kc + 4 + q];
            alo[mi][3] = sAlo[(ra + 8) * PAD + kc + 4 + q];
        }
        #pragma unroll
        for (int ni = 0; ni < 4; ni++) {
            const int nb = wn * 32 + ni * 8 + r;
            u32 bhi0 = sBhi[nb * PAD + kc + q];
            u32 bhi1 = sBhi[nb * PAD + kc + 4 + q];
            u32 blo0 = sBlo[nb * PAD + kc + q];
            u32 blo1 = sBlo[nb * PAD + kc + 4 + q];
            #pragma unroll
            for (int mi = 0; mi < 2; mi++) {
                mma_bf16(d[mi][ni], ahi[mi], bhi0, bhi1);
                mma_bf16(d[mi][ni], ahi[mi], blo0, blo1);
                mma_bf16(d[mi][ni], alo[mi], bhi0, bhi1);
            }
        }
    }

    float* Vn = g_v + (size_t)n * K768 * HW;
    #pragma unroll
    for (int mi = 0; mi < 2; mi++) {
        const int row = r0 + wm * 32 + mi * 16 + r;
        #pragma unroll
        for (int ni = 0; ni < 4; ni++) {
            const int col = p0 + wn * 32 + ni * 8 + 2 * q;
            *reinterpret_cast<float2*>(&Vn[(size_t)row * HW + col]) =
                make_float2(d[mi][ni][0], d[mi][ni][1]);
            *reinterpret_cast<float2*>(&Vn[(size_t)(row + 8) * HW + col]) =
                make_float2(d[mi][ni][2], d[mi][ni][3]);
        }
    }
}

// ===========================================================================
// combine (exact R11 known-good: 16 channels per block, m-outer, grid.y = 8)
// ===========================================================================
__global__ __launch_bounds__(256) void k_combine(
    const float* __restrict__ bias, float* __restrict__ out)
{
    const int p  = blockIdx.x * 256 + threadIdx.x;
    const int cb = blockIdx.y * 16;
    const int n  = p / HW;
    const int hw = p - n * HW;
    const int y  = hw / W;
    const int x  = hw - y * W;

    int  off[9];
    u32  okm = 0;
    #pragma unroll
    for (int l = 0; l < 9; l++) {
        const int dy = l / 3 - 1, dx = l % 3 - 1;
        const bool ok = (unsigned)(y + dy) < (unsigned)H && (unsigned)(x + dx) < (unsigned)W;
        off[l] = ok ? (dy * W + dx) : 0;
        okm |= (ok ? 1u : 0u) << l;
    }

    float acc[16];
    #pragma unroll
    for (int ci = 0; ci < 16; ci++) acc[ci] = 0.f;

    const float* Vn = g_v + (size_t)n * K768 * HW + hw;

    #pragma unroll
    for (int m = 0; m < 6; m++) {
        float bs[9];
        #pragma unroll
        for (int l = 0; l < 9; l++) {
            float t = __ldg(&g_bases[(n * 54 + m * 9 + l) * HW + hw]);
            bs[l] = (okm >> l & 1u) ? t : 0.f;
        }
        const float* Vm = Vn + (size_t)(cb * 6 + m) * HW;
        #pragma unroll
        for (int ci = 0; ci < 16; ci++) {
            const float* row = Vm + (size_t)(ci * 6) * HW;
            float s = 0.f;
            #pragma unroll
            for (int l = 0; l < 9; l++)
                s = fmaf(bs[l], __ldg(row + off[l]), s);
            acc[ci] += s;
        }
    }

    float* on = out + (size_t)n * C * HW + hw;
    #pragma unroll
    for (int ci = 0; ci < 16; ci++)
        on[(size_t)(cb + ci) * HW] = acc[ci] + __ldg(&bias[cb + ci]);
}

// ---------------------------------------------------------------------------
extern "C" void kernel_launch(void* const* d_in, const int* in_sizes, int n_in,
                              void* d_out, int out_size)
{
    const float* feat = (const float*)d_in[0];
    const float* wgt  = (const float*)d_in[1];
    const float* w1   = (const float*)d_in[2];
    const float* b1   = (const float*)d_in[3];
    const float* w2   = (const float*)d_in[4];
    const float* b2   = (const float*)d_in[5];
    const float* bbuf = (const float*)d_in[6];
    const float* coef = (const float*)d_in[7];
    const float* bias = (const float*)d_in[8];
    float* out = (float*)d_out;

    static bool attr_set = false;
    if (!attr_set) {
        cudaFuncSetAttribute(k_conv1_mma,
                             cudaFuncAttributeMaxDynamicSharedMemorySize, SM_BYTES);
        cudaFuncSetAttribute(k_vgemm_mma,
                             cudaFuncAttributeMaxDynamicSharedMemorySize, VG_SMEM);
        attr_set = true;
    }

    k_prep_in<<<(N * IN_NSTR) / 512, 512>>>(feat, wgt);
    k_prep_w1<<<(9 * 96 * 128) / 512, 512>>>(w1);
    k_prep_a<<<(K768 * 64) / 256, 256>>>(coef);

    dim3 g1(1, H / 2, N);
    k_conv1_mma<<<g1, 512, SM_BYTES>>>(b1, w2, b2, bbuf);

    dim3 g3(HW / 128, K768 / 128, N);
    k_vgemm_mma<<<g3, 512, VG_SMEM>>>();

    dim3 g4((N * HW) / 256, 8);
    k_combine<<<g4, 256>>>(bias, out);
}

// round 16
// speedup vs baseline: 1.4556x; 1.0478x over previous
#include <cuda_runtime.h>
#include <cuda_bf16.h>
#include <math.h>

typedef unsigned long long u64;
typedef unsigned int u32;

__device__ __forceinline__ unsigned smem_u32p(const void* p) {
    unsigned a;
    asm("{ .reg .u64 t; cvta.to.shared.u64 t, %1; cvt.u32.u64 %0, t; }" : "=r"(a) : "l"(p));
    return a;
}
__device__ __forceinline__ void cp16(unsigned dst, const void* src) {
    asm volatile("cp.async.cg.shared.global [%0], [%1], 16;" :: "r"(dst), "l"(src));
}
__device__ __forceinline__ void cp4(unsigned dst, const void* src) {
    asm volatile("cp.async.ca.shared.global [%0], [%1], 4;" :: "r"(dst), "l"(src));
}
__device__ __forceinline__ void cp_commit() { asm volatile("cp.async.commit_group;"); }
template <int Nw>
__device__ __forceinline__ void cp_wait() { asm volatile("cp.async.wait_group %0;" :: "n"(Nw)); }

// Problem constants
constexpr int N   = 8;
constexpr int C   = 128;
constexpr int CW  = 64;
constexpr int CIN = C + CW;   // 192
constexpr int H   = 96;
constexpr int W   = 96;
constexpr int HW  = H * W;    // 9216
constexpr int K768 = C * 6;   // 768

// Static scratch
__device__ float g_bases[N * 54 * HW];
__device__ float g_v    [(size_t)N * K768 * HW];
__device__ __align__(16) u32 g_ahi [K768 * 64];
__device__ __align__(16) u32 g_alo [K768 * 64];
__device__ __align__(16) u32 g_w1hi[9 * 96 * 128];
__device__ __align__(16) u32 g_w1lo[9 * 96 * 128];
// pre-split, pre-padded inputs: [n][96 ci2][98 rows][104 cols]
constexpr int IN_CI = 96;
constexpr int IN_R  = 98;
constexpr int IN_CSTR = 104;
constexpr int IN_NSTR = IN_CI * IN_R * IN_CSTR;
__device__ __align__(16) u32 g_inhi[N * IN_NSTR];
__device__ __align__(16) u32 g_inlo[N * IN_NSTR];

// ===========================================================================
__device__ __forceinline__ void split2(float f0, float f1, u32& hi, u32& lo) {
    __nv_bfloat16 h0 = __float2bfloat16_rn(f0);
    __nv_bfloat16 h1 = __float2bfloat16_rn(f1);
    float l0f = f0 - __bfloat162float(h0);
    float l1f = f1 - __bfloat162float(h1);
    __nv_bfloat16 l0 = __float2bfloat16_rn(l0f);
    __nv_bfloat16 l1 = __float2bfloat16_rn(l1f);
    hi = ((u32)__bfloat16_as_ushort(h1) << 16) | (u32)__bfloat16_as_ushort(h0);
    lo = ((u32)__bfloat16_as_ushort(l1) << 16) | (u32)__bfloat16_as_ushort(l0);
}

__device__ __forceinline__ void mma_bf16(float d[4], const u32 a[4], u32 b0, u32 b1) {
    asm volatile(
        "mma.sync.aligned.m16n8k16.row.col.f32.bf16.bf16.f32 "
        "{%0,%1,%2,%3}, {%4,%5,%6,%7}, {%8,%9}, {%0,%1,%2,%3};"
        : "+f"(d[0]), "+f"(d[1]), "+f"(d[2]), "+f"(d[3])
        : "r"(a[0]), "r"(a[1]), "r"(a[2]), "r"(a[3]), "r"(b0), "r"(b1));
}

// ===========================================================================
// fused prep kernel: [0, PIN_B) -> input split, then w1, then coef
// ===========================================================================
constexpr int PIN_B = (N * IN_NSTR) / 512;           // 15288
constexpr int PW1_B = (9 * 96 * 128) / 512;          // 216
constexpr int PA_B  = (K768 * 64) / 512;             // 96
constexpr int PREP_B = PIN_B + PW1_B + PA_B;

__global__ __launch_bounds__(512) void k_prep(
    const float* __restrict__ feat, const float* __restrict__ wgt,
    const float* __restrict__ w1,   const float* __restrict__ coef)
{
    const int b = blockIdx.x;
    if (b < PIN_B) {
        const int idx = b * 512 + threadIdx.x;
        const int n   = idx / IN_NSTR;
        int rem = idx - n * IN_NSTR;
        const int ci2 = rem / (IN_R * IN_CSTR);
        rem -= ci2 * (IN_R * IN_CSTR);
        const int row = rem / IN_CSTR;
        const int col = rem - row * IN_CSTR;
        float f0 = 0.f, f1 = 0.f;
        if (row >= 1 && row <= 96 && col >= 1 && col <= 96) {
            const int y = row - 1, x = col - 1;
            const float* bp = (ci2 < 64)
                ? &feat[((n * C + 2 * ci2) * H + y) * W + x]
                : &wgt [((n * CW + 2 * (ci2 - 64)) * H + y) * W + x];
            f0 = bp[0];
            f1 = bp[HW];
        }
        u32 hi, lo;
        split2(f0, f1, hi, lo);
        g_inhi[idx] = hi;
        g_inlo[idx] = lo;
    } else if (b < PIN_B + PW1_B) {
        const int idx = (b - PIN_B) * 512 + threadIdx.x;
        const int tap = idx / (96 * 128);
        const int rem = idx - tap * 96 * 128;
        const int ci2 = rem >> 7;
        const int co  = rem & 127;
        const float f0 = w1[(co * CIN + 2 * ci2)     * 9 + tap];
        const float f1 = w1[(co * CIN + 2 * ci2 + 1) * 9 + tap];
        u32 hi, lo;
        split2(f0, f1, hi, lo);
        g_w1hi[idx] = hi;
        g_w1lo[idx] = lo;
    } else {
        const int idx = (b - PIN_B - PW1_B) * 512 + threadIdx.x;
        const int rg = idx >> 6;
        const int k2 = idx & 63;
        const int c  = rg / 6;
        const int mm = rg - c * 6;
        const int k  = 2 * k2;
        u32 hi, lo;
        split2(coef[c * K768 + k * 6 + mm], coef[c * K768 + (k + 1) * 6 + mm], hi, lo);
        g_ahi[idx] = hi;
        g_alo[idx] = lo;
    }
}

// ===========================================================================
// fused main kernel: blocks [0,384) = conv1 path, [384, 3840) = vgemm path.
// ===========================================================================
constexpr int CISTR = 424;
constexpr int IHALF = 24 * CISTR;
constexpr int IBSZ  = 2 * IHALF;
constexpr int AB    = 2 * IBSZ;
constexpr int ASTR  = 136;
constexpr int ATILE = 24 * ASTR;
constexpr int SM_U32  = AB + 4 * ATILE;
constexpr int SM_BYTES = SM_U32 * 4;       // 215040 B

constexpr int PAD = 68;                    // vgemm smem layout (fits inside SM_BYTES)

constexpr int CONV1_B = N * (H / 2);       // 384
constexpr int VG_B    = (HW / 128) * (K768 / 128) * N;  // 3456
constexpr int MAIN_B  = CONV1_B + VG_B;    // 3840

__device__ __forceinline__ void conv1_path(
    u32* sm, int n, int y0,
    const float* __restrict__ b1,
    const float* __restrict__ w2, const float* __restrict__ b2,
    const float* __restrict__ bbuf)
{
    const int tid  = threadIdx.x;
    const int wid  = tid >> 5;
    const int lane = tid & 31;
    const int wm = wid & 3;
    const int wn = wid >> 2;
    const int r  = lane >> 2;
    const int q  = lane & 3;

    float d[2][6][4];
    #pragma unroll
    for (int mi = 0; mi < 2; mi++)
        #pragma unroll
        for (int ni = 0; ni < 6; ni++)
            #pragma unroll
            for (int e = 0; e < 4; e++) d[mi][ni][e] = 0.f;

    auto stageA = [&](int tap, int cg, int buf) {
        const u32* srcH = g_w1hi + (tap * 96 + cg * 24) * 128;
        const u32* srcL = g_w1lo + (tap * 96 + cg * 24) * 128;
        u32* dH = sm + AB + buf * 2 * ATILE;
        u32* dL = dH + ATILE;
        #pragma unroll
        for (int it = 0; it < 2; it++) {
            int i = tid + it * 512;
            if (i < 768) {
                int ci2l = i >> 5;
                int c4   = (i & 31) * 4;
                cp16(smem_u32p(&dH[ci2l * ASTR + c4]), &srcH[ci2l * 128 + c4]);
                cp16(smem_u32p(&dL[ci2l * ASTR + c4]), &srcL[ci2l * 128 + c4]);
            }
        }
    };

    auto stageInRange = [&](int cgT, int buf, int c0, int c1) {
        const int ibase = buf * IBSZ;
        const int cnt = (c1 - c0) * 200;
        for (int i = tid; i < cnt; i += 512) {
            int ci2o = i / 200;
            int rem  = i - ci2o * 200;
            int arr  = rem / 100;
            int rem2 = rem - arr * 100;
            int rr   = rem2 / 25;
            int f4   = rem2 - rr * 25;
            int dst  = ibase + arr * IHALF + (c0 + ci2o) * CISTR + rr * 100 + f4 * 4;
            int src  = ((n * IN_CI + cgT * 24 + c0 + ci2o) * IN_R + y0 + rr) * IN_CSTR + f4 * 4;
            cp16(smem_u32p(&sm[dst]), arr ? &g_inlo[src] : &g_inhi[src]);
        }
    };

    stageInRange(0, 0, 0, 24);
    stageA(0, 0, 0);
    cp_commit();

    const int prow = wn >> 1;
    const int px0  = (wn & 1) * 48;

    int it = 0;
    for (int cg = 0; cg < 4; cg++) {
        const int ib = (cg & 1) * IBSZ;
        for (int tap = 0; tap < 9; tap++, it++) {
            const int abuf = it & 1;
            cp_wait<0>();
            __syncthreads();
            if (tap >= 2 && tap <= 5 && cg < 3)
                stageInRange(cg + 1, (cg + 1) & 1, (tap - 2) * 6, (tap - 1) * 6);
            if (it + 1 < 36) {
                stageA((it + 1) % 9, (it + 1) / 9, abuf ^ 1);
                cp_commit();
            }

            const int ky = tap / 3, kx = tap % 3;
            const u32* AH = sm + AB + abuf * 2 * ATILE;
            const u32* AL = AH + ATILE;
            const int boff = (prow + ky) * 100 + kx + px0;

            #pragma unroll
            for (int s = 0; s < 3; s++) {
                const int kb2 = s * 8;
                u32 ahi[2][4], alo[2][4];
                #pragma unroll
                for (int mi = 0; mi < 2; mi++) {
                    const int ra = wm * 32 + mi * 16 + r;
                    ahi[mi][0] = AH[(kb2 + q) * ASTR + ra];
                    ahi[mi][1] = AH[(kb2 + q) * ASTR + ra + 8];
                    ahi[mi][2] = AH[(kb2 + 4 + q) * ASTR + ra];
                    ahi[mi][3] = AH[(kb2 + 4 + q) * ASTR + ra + 8];
                    alo[mi][0] = AL[(kb2 + q) * ASTR + ra];
                    alo[mi][1] = AL[(kb2 + q) * ASTR + ra + 8];
                    alo[mi][2] = AL[(kb2 + 4 + q) * ASTR + ra];
                    alo[mi][3] = AL[(kb2 + 4 + q) * ASTR + ra + 8];
                }
                #pragma unroll
                for (int ni = 0; ni < 6; ni++) {
                    const int a0 = (kb2 + q) * CISTR + boff + ni * 8 + r;
                    const int a1 = (kb2 + 4 + q) * CISTR + boff + ni * 8 + r;
                    const u32 bhi0 = sm[ib + a0];
                    const u32 bhi1 = sm[ib + a1];
                    const u32 blo0 = sm[ib + IHALF + a0];
                    const u32 blo1 = sm[ib + IHALF + a1];
                    #pragma unroll
                    for (int mi = 0; mi < 2; mi++) {
                        mma_bf16(d[mi][ni], ahi[mi], bhi0, bhi1);
                        mma_bf16(d[mi][ni], ahi[mi], blo0, blo1);
                        mma_bf16(d[mi][ni], alo[mi], bhi0, bhi1);
                    }
                }
            }
        }
    }
    __syncthreads();

    float* sH = reinterpret_cast<float*>(sm);
    #pragma unroll
    for (int mi = 0; mi < 2; mi++) {
        const int row = wm * 32 + mi * 16 + r;
        const float bb0 = b1[row];
        const float bb1 = b1[row + 8];
        #pragma unroll
        for (int ni = 0; ni < 6; ni++) {
            const int px = prow * 96 + px0 + ni * 8 + 2 * q;
            sH[row * 194 + px]           = tanhf(d[mi][ni][0] + bb0);
            sH[row * 194 + px + 1]       = tanhf(d[mi][ni][1] + bb0);
            sH[(row + 8) * 194 + px]     = tanhf(d[mi][ni][2] + bb1);
            sH[(row + 8) * 194 + px + 1] = tanhf(d[mi][ni][3] + bb1);
        }
    }
    __syncthreads();

    float* sW2 = reinterpret_cast<float*>(sm) + 24832;
    float* sBv = reinterpret_cast<float*>(sm) + 29440;
    float* sBB = reinterpret_cast<float*>(sm) + 36544;
    #pragma unroll
    for (int itr = 0; itr < 9; itr++) {
        int i = tid + itr * 512;
        int ci = i / 36;
        int ch = i - ci * 36;
        sW2[i] = w2[ch * 128 + ci];
    }
    if (tid < 54) sBB[tid] = bbuf[tid];
    __syncthreads();

    if (tid < 384) {
        const int px  = tid >> 1;
        const int ch0 = (tid & 1) * 18;
        float a2c[18];
        #pragma unroll
        for (int qq = 0; qq < 18; qq++) a2c[qq] = 0.f;
        for (int ci = 0; ci < 128; ci++) {
            const float hv = sH[ci * 194 + px];
            const float* wr = &sW2[ci * 36 + ch0];
            #pragma unroll
            for (int qq = 0; qq < 18; qq++)
                a2c[qq] = fmaf(wr[qq], hv, a2c[qq]);
        }
        #pragma unroll
        for (int qq = 0; qq < 18; qq++)
            sBv[px * 37 + ch0 + qq] = tanhf(a2c[qq] + b2[ch0 + qq]);
    }
    __syncthreads();

    for (int i = tid; i < 54 * 192; i += 512) {
        const int j  = i / 192;
        const int px = i - j * 192;
        const int row = px / 96;
        const int x   = px - row * 96;
        const int m  = j / 9;
        const int l  = j - m * 9;
        float s = 0.f;
        #pragma unroll
        for (int t = 0; t < 6; t++)
            s = fmaf(sBv[px * 37 + m * 6 + t], sBB[t * 9 + l], s);
        g_bases[(n * 54 + j) * HW + (y0 + row) * W + x] = s;
    }
}

__device__ __forceinline__ void vgemm_path(u32* vsm, int n, int r0, int p0)
{
    u32* sAhi = vsm;
    u32* sAlo = vsm + 128 * PAD;
    u32* sBhi = vsm + 2 * 128 * PAD;
    u32* sBlo = vsm + 3 * 128 * PAD;

    const int tid = threadIdx.x;

    #pragma unroll
    for (int it = 0; it < 4; it++) {
        int i = tid + it * 512;
        int m  = i >> 4;
        int k4 = i & 15;
        cp16(smem_u32p(&sAhi[m * PAD + k4 * 4]), &g_ahi[(r0 + m) * 64 + k4 * 4]);
        cp16(smem_u32p(&sAlo[m * PAD + k4 * 4]), &g_alo[(r0 + m) * 64 + k4 * 4]);
    }
    #pragma unroll
    for (int it = 0; it < 16; it++) {
        int idx = tid + it * 512;
        int k2 = idx >> 7;
        int p  = idx & 127;
        int gp = p0 + p;
        int row = gp / 96;
        int col = gp - row * 96;
        int src = ((n * IN_CI + k2) * IN_R + row + 1) * IN_CSTR + col + 1;
        cp4(smem_u32p(&sBhi[p * PAD + k2]), &g_inhi[src]);
        cp4(smem_u32p(&sBlo[p * PAD + k2]), &g_inlo[src]);
    }
    cp_commit();
    cp_wait<0>();
    __syncthreads();

    const int wid = tid >> 5;
    const int lane = tid & 31;
    const int wm = wid & 3;
    const int wn = wid >> 2;
    const int r  = lane >> 2;
    const int q  = lane & 3;

    float d[2][4][4];
    #pragma unroll
    for (int mi = 0; mi < 2; mi++)
        #pragma unroll
        for (int ni = 0; ni < 4; ni++)
            #pragma unroll
            for (int e = 0; e < 4; e++) d[mi][ni][e] = 0.f;

    #pragma unroll
    for (int ks = 0; ks < 8; ks++) {
        const int kc = ks * 8;
        u32 ahi[2][4], alo[2][4];
        #pragma unroll
        for (int mi = 0; mi < 2; mi++) {
            const int ra = wm * 32 + mi * 16 + r;
            ahi[mi][0] = sAhi[ra * PAD + kc + q];
            ahi[mi][1] = sAhi[(ra + 8) * PAD + kc + q];
            ahi[mi][2] = sAhi[ra * PAD + kc + 4 + q];
            ahi[mi][3] = sAhi[(ra + 8) * PAD + kc + 4 + q];
            alo[mi][0] = sAlo[ra * PAD + kc + q];
            alo[mi][1] = sAlo[(ra + 8) * PAD + kc + q];
            alo[mi][2] = sAlo[ra * PAD + kc + 4 + q];
            alo[mi][3] = sAlo[(ra + 8) * PAD + kc + 4 + q];
        }
        #pragma unroll
        for (int ni = 0; ni < 4; ni++) {
            const int nb = wn * 32 + ni * 8 + r;
            u32 bhi0 = sBhi[nb * PAD + kc + q];
            u32 bhi1 = sBhi[nb * PAD + kc + 4 + q];
            u32 blo0 = sBlo[nb * PAD + kc + q];
            u32 blo1 = sBlo[nb * PAD + kc + 4 + q];
            #pragma unroll
            for (int mi = 0; mi < 2; mi++) {
                mma_bf16(d[mi][ni], ahi[mi], bhi0, bhi1);
                mma_bf16(d[mi][ni], ahi[mi], blo0, blo1);
                mma_bf16(d[mi][ni], alo[mi], bhi0, bhi1);
            }
        }
    }

    float* Vn = g_v + (size_t)n * K768 * HW;
    #pragma unroll
    for (int mi = 0; mi < 2; mi++) {
        const int row = r0 + wm * 32 + mi * 16 + r;
        #pragma unroll
        for (int ni = 0; ni < 4; ni++) {
            const int col = p0 + wn * 32 + ni * 8 + 2 * q;
            *reinterpret_cast<float2*>(&Vn[(size_t)row * HW + col]) =
                make_float2(d[mi][ni][0], d[mi][ni][1]);
            *reinterpret_cast<float2*>(&Vn[(size_t)(row + 8) * HW + col]) =
                make_float2(d[mi][ni][2], d[mi][ni][3]);
        }
    }
}

__global__ __launch_bounds__(512, 1) void k_main(
    const float* __restrict__ b1,
    const float* __restrict__ w2, const float* __restrict__ b2,
    const float* __restrict__ bbuf)
{
    extern __shared__ u32 sm[];
    const int b = blockIdx.x;
    if (b < CONV1_B) {
        const int n  = b / (H / 2);
        const int y0 = (b - n * (H / 2)) * 2;
        conv1_path(sm, n, y0, b1, w2, b2, bbuf);
    } else {
        const int v   = b - CONV1_B;
        const int n   = v / 432;
        const int rem = v - n * 432;
        const int r0  = (rem / 72) * 128;
        const int p0  = (rem - (rem / 72) * 72) * 128;
        vgemm_path(sm, n, r0, p0);
    }
}

// ===========================================================================
// combine (R11 known-good: 16 channels per block, m-outer, grid.y = 8)
// ===========================================================================
__global__ __launch_bounds__(256) void k_combine(
    const float* __restrict__ bias, float* __restrict__ out)
{
    const int p  = blockIdx.x * 256 + threadIdx.x;
    const int cb = blockIdx.y * 16;
    const int n  = p / HW;
    const int hw = p - n * HW;
    const int y  = hw / W;
    const int x  = hw - y * W;

    int  off[9];
    u32  okm = 0;
    #pragma unroll
    for (int l = 0; l < 9; l++) {
        const int dy = l / 3 - 1, dx = l % 3 - 1;
        const bool ok = (unsigned)(y + dy) < (unsigned)H && (unsigned)(x + dx) < (unsigned)W;
        off[l] = ok ? (dy * W + dx) : 0;
        okm |= (ok ? 1u : 0u) << l;
    }

    float acc[16];
    #pragma unroll
    for (int ci = 0; ci < 16; ci++) acc[ci] = 0.f;

    const float* Vn = g_v + (size_t)n * K768 * HW + hw;

    #pragma unroll
    for (int m = 0; m < 6; m++) {
        float bs[9];
        #pragma unroll
        for (int l = 0; l < 9; l++) {
            float t = __ldg(&g_bases[(n * 54 + m * 9 + l) * HW + hw]);
            bs[l] = (okm >> l & 1u) ? t : 0.f;
        }
        const float* Vm = Vn + (size_t)(cb * 6 + m) * HW;
        #pragma unroll
        for (int ci = 0; ci < 16; ci++) {
            const float* row = Vm + (size_t)(ci * 6) * HW;
            float s = 0.f;
            #pragma unroll
            for (int l = 0; l < 9; l++)
                s = fmaf(bs[l], __ldg(row + off[l]), s);
            acc[ci] += s;
        }
    }

    float* on = out + (size_t)n * C * HW + hw;
    #pragma unroll
    for (int ci = 0; ci < 16; ci++)
        on[(size_t)(cb + ci) * HW] = acc[ci] + __ldg(&bias[cb + ci]);
}

// ---------------------------------------------------------------------------
extern "C" void kernel_launch(void* const* d_in, const int* in_sizes, int n_in,
                              void* d_out, int out_size)
{
    const float* feat = (const float*)d_in[0];
    const float* wgt  = (const float*)d_in[1];
    const float* w1   = (const float*)d_in[2];
    const float* b1   = (const float*)d_in[3];
    const float* w2   = (const float*)d_in[4];
    const float* b2   = (const float*)d_in[5];
    const float* bbuf = (const float*)d_in[6];
    const float* coef = (const float*)d_in[7];
    const float* bias = (const float*)d_in[8];
    float* out = (float*)d_out;

    static bool attr_set = false;
    if (!attr_set) {
        cudaFuncSetAttribute(k_main,
                             cudaFuncAttributeMaxDynamicSharedMemorySize, SM_BYTES);
        attr_set = true;
    }

    k_prep<<<PREP_B, 512>>>(feat, wgt, w1, coef);

    k_main<<<MAIN_B, 512, SM_BYTES>>>(b1, w2, b2, bbuf);

    dim3 g4((N * HW) / 256, 8);
    k_combine<<<g4, 256>>>(bias, out);
}

// round 17
// speedup vs baseline: 1.5202x; 1.0444x over previous
#include <cuda_runtime.h>
#include <cuda_bf16.h>
#include <math.h>

typedef unsigned long long u64;
typedef unsigned int u32;

__device__ __forceinline__ unsigned smem_u32p(const void* p) {
    unsigned a;
    asm("{ .reg .u64 t; cvta.to.shared.u64 t, %1; cvt.u32.u64 %0, t; }" : "=r"(a) : "l"(p));
    return a;
}
__device__ __forceinline__ void cp16(unsigned dst, const void* src) {
    asm volatile("cp.async.cg.shared.global [%0], [%1], 16;" :: "r"(dst), "l"(src));
}
__device__ __forceinline__ void cp_commit() { asm volatile("cp.async.commit_group;"); }
template <int Nw>
__device__ __forceinline__ void cp_wait() { asm volatile("cp.async.wait_group %0;" :: "n"(Nw)); }

// Problem constants
constexpr int N   = 8;
constexpr int C   = 128;
constexpr int CW  = 64;
constexpr int CIN = C + CW;   // 192
constexpr int H   = 96;
constexpr int W   = 96;
constexpr int HW  = H * W;    // 9216
constexpr int K768 = C * 6;   // 768

// Static scratch
__device__ float g_bases[N * 54 * HW];
__device__ float g_v    [(size_t)N * K768 * HW];
__device__ __align__(16) u32 g_ahi [K768 * 64];
__device__ __align__(16) u32 g_alo [K768 * 64];
__device__ __align__(16) u32 g_w1hi[9 * 96 * 128];
__device__ __align__(16) u32 g_w1lo[9 * 96 * 128];
// pre-split, pre-padded inputs: [n][96 ci2][98 rows][104 cols]
// column layout: idx 3 = x=-1 (halo), idx 4..99 = x 0..95, rest zero.
// => pixel col 0 at idx 4 (16B aligned) for vgemm cp16 staging.
constexpr int IN_CI = 96;
constexpr int IN_R  = 98;
constexpr int IN_CSTR = 104;
constexpr int IN_NSTR = IN_CI * IN_R * IN_CSTR;
__device__ __align__(16) u32 g_inhi[N * IN_NSTR];
__device__ __align__(16) u32 g_inlo[N * IN_NSTR];

// ===========================================================================
__device__ __forceinline__ void split2(float f0, float f1, u32& hi, u32& lo) {
    __nv_bfloat16 h0 = __float2bfloat16_rn(f0);
    __nv_bfloat16 h1 = __float2bfloat16_rn(f1);
    float l0f = f0 - __bfloat162float(h0);
    float l1f = f1 - __bfloat162float(h1);
    __nv_bfloat16 l0 = __float2bfloat16_rn(l0f);
    __nv_bfloat16 l1 = __float2bfloat16_rn(l1f);
    hi = ((u32)__bfloat16_as_ushort(h1) << 16) | (u32)__bfloat16_as_ushort(h0);
    lo = ((u32)__bfloat16_as_ushort(l1) << 16) | (u32)__bfloat16_as_ushort(l0);
}

__device__ __forceinline__ void mma_bf16(float d[4], const u32 a[4], u32 b0, u32 b1) {
    asm volatile(
        "mma.sync.aligned.m16n8k16.row.col.f32.bf16.bf16.f32 "
        "{%0,%1,%2,%3}, {%4,%5,%6,%7}, {%8,%9}, {%0,%1,%2,%3};"
        : "+f"(d[0]), "+f"(d[1]), "+f"(d[2]), "+f"(d[3])
        : "r"(a[0]), "r"(a[1]), "r"(a[2]), "r"(a[3]), "r"(b0), "r"(b1));
}

// ===========================================================================
// fused prep kernel
// ===========================================================================
constexpr int PIN_B = (N * IN_NSTR) / 512;           // 15288
constexpr int PW1_B = (9 * 96 * 128) / 512;          // 216
constexpr int PA_B  = (K768 * 64) / 512;             // 96
constexpr int PREP_B = PIN_B + PW1_B + PA_B;

__global__ __launch_bounds__(512) void k_prep(
    const float* __restrict__ feat, const float* __restrict__ wgt,
    const float* __restrict__ w1,   const float* __restrict__ coef)
{
    const int b = blockIdx.x;
    if (b < PIN_B) {
        const int idx = b * 512 + threadIdx.x;
        const int n   = idx / IN_NSTR;
        int rem = idx - n * IN_NSTR;
        const int ci2 = rem / (IN_R * IN_CSTR);
        rem -= ci2 * (IN_R * IN_CSTR);
        const int row = rem / IN_CSTR;
        const int col = rem - row * IN_CSTR;
        float f0 = 0.f, f1 = 0.f;
        // row index r = y+1 (rows 1..96 valid); col index c = x+4 (4..99 valid)
        if (row >= 1 && row <= 96 && col >= 4 && col <= 99) {
            const int y = row - 1, x = col - 4;
            const float* bp = (ci2 < 64)
                ? &feat[((n * C + 2 * ci2) * H + y) * W + x]
                : &wgt [((n * CW + 2 * (ci2 - 64)) * H + y) * W + x];
            f0 = bp[0];
            f1 = bp[HW];
        }
        u32 hi, lo;
        split2(f0, f1, hi, lo);
        g_inhi[idx] = hi;
        g_inlo[idx] = lo;
    } else if (b < PIN_B + PW1_B) {
        const int idx = (b - PIN_B) * 512 + threadIdx.x;
        const int tap = idx / (96 * 128);
        const int rem = idx - tap * 96 * 128;
        const int ci2 = rem >> 7;
        const int co  = rem & 127;
        const float f0 = w1[(co * CIN + 2 * ci2)     * 9 + tap];
        const float f1 = w1[(co * CIN + 2 * ci2 + 1) * 9 + tap];
        u32 hi, lo;
        split2(f0, f1, hi, lo);
        g_w1hi[idx] = hi;
        g_w1lo[idx] = lo;
    } else {
        const int idx = (b - PIN_B - PW1_B) * 512 + threadIdx.x;
        const int rg = idx >> 6;
        const int k2 = idx & 63;
        const int c  = rg / 6;
        const int mm = rg - c * 6;
        const int k  = 2 * k2;
        u32 hi, lo;
        split2(coef[c * K768 + k * 6 + mm], coef[c * K768 + (k + 1) * 6 + mm], hi, lo);
        g_ahi[idx] = hi;
        g_alo[idx] = lo;
    }
}

// ===========================================================================
// fused main kernel: blocks [0,384) = conv1 path, [384, 3840) = vgemm path.
// ===========================================================================
constexpr int CISTR = 424;                 // 4 rows x 104 + 8 pad; mod 32 == 8
constexpr int IHALF = 24 * CISTR;
constexpr int IBSZ  = 2 * IHALF;
constexpr int AB    = 2 * IBSZ;
constexpr int ASTR  = 136;
constexpr int ATILE = 24 * ASTR;
constexpr int SM_U32  = AB + 4 * ATILE;
constexpr int SM_BYTES = SM_U32 * 4;       // 215040 B

constexpr int PAD  = 68;                   // vgemm A smem stride [m][k2]
constexpr int PADB = 136;                  // vgemm B smem stride [k2][p]

constexpr int CONV1_B = N * (H / 2);       // 384
constexpr int VG_B    = (HW / 128) * (K768 / 128) * N;  // 3456
constexpr int MAIN_B  = CONV1_B + VG_B;    // 3840

__device__ __forceinline__ void conv1_path(
    u32* sm, int n, int y0,
    const float* __restrict__ b1,
    const float* __restrict__ w2, const float* __restrict__ b2,
    const float* __restrict__ bbuf)
{
    const int tid  = threadIdx.x;
    const int wid  = tid >> 5;
    const int lane = tid & 31;
    const int wm = wid & 3;
    const int wn = wid >> 2;
    const int r  = lane >> 2;
    const int q  = lane & 3;

    float d[2][6][4];
    #pragma unroll
    for (int mi = 0; mi < 2; mi++)
        #pragma unroll
        for (int ni = 0; ni < 6; ni++)
            #pragma unroll
            for (int e = 0; e < 4; e++) d[mi][ni][e] = 0.f;

    auto stageA = [&](int tap, int cg, int buf) {
        const u32* srcH = g_w1hi + (tap * 96 + cg * 24) * 128;
        const u32* srcL = g_w1lo + (tap * 96 + cg * 24) * 128;
        u32* dH = sm + AB + buf * 2 * ATILE;
        u32* dL = dH + ATILE;
        #pragma unroll
        for (int it = 0; it < 2; it++) {
            int i = tid + it * 512;
            if (i < 768) {
                int ci2l = i >> 5;
                int c4   = (i & 31) * 4;
                cp16(smem_u32p(&dH[ci2l * ASTR + c4]), &srcH[ci2l * 128 + c4]);
                cp16(smem_u32p(&dL[ci2l * ASTR + c4]), &srcL[ci2l * 128 + c4]);
            }
        }
    };

    // stage ci2 range: full 104-col rows (26 cp16 per row), rows y0-1..y0+2
    auto stageInRange = [&](int cgT, int buf, int c0, int c1) {
        const int ibase = buf * IBSZ;
        const int cnt = (c1 - c0) * 208;    // per ci2: 2 arrays x 4 rows x 26 f4
        for (int i = tid; i < cnt; i += 512) {
            int ci2o = i / 208;
            int rem  = i - ci2o * 208;
            int arr  = rem / 104;
            int rem2 = rem - arr * 104;
            int rr   = rem2 / 26;
            int f4   = rem2 - rr * 26;
            int dst  = ibase + arr * IHALF + (c0 + ci2o) * CISTR + rr * 104 + f4 * 4;
            int src  = ((n * IN_CI + cgT * 24 + c0 + ci2o) * IN_R + y0 + rr) * IN_CSTR + f4 * 4;
            cp16(smem_u32p(&sm[dst]), arr ? &g_inlo[src] : &g_inhi[src]);
        }
    };

    stageInRange(0, 0, 0, 24);
    stageA(0, 0, 0);
    cp_commit();

    const int prow = wn >> 1;
    const int px0  = (wn & 1) * 48;

    int it = 0;
    for (int cg = 0; cg < 4; cg++) {
        const int ib = (cg & 1) * IBSZ;
        for (int tap = 0; tap < 9; tap++, it++) {
            const int abuf = it & 1;
            cp_wait<0>();
            __syncthreads();
            if (tap >= 2 && tap <= 5 && cg < 3)
                stageInRange(cg + 1, (cg + 1) & 1, (tap - 2) * 6, (tap - 1) * 6);
            if (it + 1 < 36) {
                stageA((it + 1) % 9, (it + 1) / 9, abuf ^ 1);
                cp_commit();
            }

            const int ky = tap / 3, kx = tap % 3;
            const u32* AH = sm + AB + abuf * 2 * ATILE;
            const u32* AL = AH + ATILE;
            // halo col -1 at index 3: pixel x tap kx -> index x + 3 + kx
            const int boff = (prow + ky) * 104 + kx + 3 + px0;

            #pragma unroll
            for (int s = 0; s < 3; s++) {
                const int kb2 = s * 8;
                u32 ahi[2][4], alo[2][4];
                #pragma unroll
                for (int mi = 0; mi < 2; mi++) {
                    const int ra = wm * 32 + mi * 16 + r;
                    ahi[mi][0] = AH[(kb2 + q) * ASTR + ra];
                    ahi[mi][1] = AH[(kb2 + q) * ASTR + ra + 8];
                    ahi[mi][2] = AH[(kb2 + 4 + q) * ASTR + ra];
                    ahi[mi][3] = AH[(kb2 + 4 + q) * ASTR + ra + 8];
                    alo[mi][0] = AL[(kb2 + q) * ASTR + ra];
                    alo[mi][1] = AL[(kb2 + q) * ASTR + ra + 8];
                    alo[mi][2] = AL[(kb2 + 4 + q) * ASTR + ra];
                    alo[mi][3] = AL[(kb2 + 4 + q) * ASTR + ra + 8];
                }
                #pragma unroll
                for (int ni = 0; ni < 6; ni++) {
                    const int a0 = (kb2 + q) * CISTR + boff + ni * 8 + r;
                    const int a1 = (kb2 + 4 + q) * CISTR + boff + ni * 8 + r;
                    const u32 bhi0 = sm[ib + a0];
                    const u32 bhi1 = sm[ib + a1];
                    const u32 blo0 = sm[ib + IHALF + a0];
                    const u32 blo1 = sm[ib + IHALF + a1];
                    #pragma unroll
                    for (int mi = 0; mi < 2; mi++) {
                        mma_bf16(d[mi][ni], ahi[mi], bhi0, bhi1);
                        mma_bf16(d[mi][ni], ahi[mi], blo0, blo1);
                        mma_bf16(d[mi][ni], alo[mi], bhi0, bhi1);
                    }
                }
            }
        }
    }
    __syncthreads();

    float* sH = reinterpret_cast<float*>(sm);
    #pragma unroll
    for (int mi = 0; mi < 2; mi++) {
        const int row = wm * 32 + mi * 16 + r;
        const float bb0 = b1[row];
        const float bb1 = b1[row + 8];
        #pragma unroll
        for (int ni = 0; ni < 6; ni++) {
            const int px = prow * 96 + px0 + ni * 8 + 2 * q;
            sH[row * 194 + px]           = tanhf(d[mi][ni][0] + bb0);
            sH[row * 194 + px + 1]       = tanhf(d[mi][ni][1] + bb0);
            sH[(row + 8) * 194 + px]     = tanhf(d[mi][ni][2] + bb1);
            sH[(row + 8) * 194 + px + 1] = tanhf(d[mi][ni][3] + bb1);
        }
    }
    __syncthreads();

    float* sW2 = reinterpret_cast<float*>(sm) + 24832;
    float* sBv = reinterpret_cast<float*>(sm) + 29440;
    float* sBB = reinterpret_cast<float*>(sm) + 36544;
    #pragma unroll
    for (int itr = 0; itr < 9; itr++) {
        int i = tid + itr * 512;
        int ci = i / 36;
        int ch = i - ci * 36;
        sW2[i] = w2[ch * 128 + ci];
    }
    if (tid < 54) sBB[tid] = bbuf[tid];
    __syncthreads();

    if (tid < 384) {
        const int px  = tid >> 1;
        const int ch0 = (tid & 1) * 18;
        float a2c[18];
        #pragma unroll
        for (int qq = 0; qq < 18; qq++) a2c[qq] = 0.f;
        for (int ci = 0; ci < 128; ci++) {
            const float hv = sH[ci * 194 + px];
            const float* wr = &sW2[ci * 36 + ch0];
            #pragma unroll
            for (int qq = 0; qq < 18; qq++)
                a2c[qq] = fmaf(wr[qq], hv, a2c[qq]);
        }
        #pragma unroll
        for (int qq = 0; qq < 18; qq++)
            sBv[px * 37 + ch0 + qq] = tanhf(a2c[qq] + b2[ch0 + qq]);
    }
    __syncthreads();

    for (int i = tid; i < 54 * 192; i += 512) {
        const int j  = i / 192;
        const int px = i - j * 192;
        const int row = px / 96;
        const int x   = px - row * 96;
        const int m  = j / 9;
        const int l  = j - m * 9;
        float s = 0.f;
        #pragma unroll
        for (int t = 0; t < 6; t++)
            s = fmaf(sBv[px * 37 + m * 6 + t], sBB[t * 9 + l], s);
        g_bases[(n * 54 + j) * HW + (y0 + row) * W + x] = s;
    }
}

__device__ __forceinline__ void vgemm_path(u32* vsm, int n, int r0, int p0)
{
    u32* sAhi = vsm;                       // [128][68]
    u32* sAlo = vsm + 8704;
    u32* sBhi = vsm + 2 * 8704;            // [64][136]
    u32* sBlo = vsm + 3 * 8704;

    const int tid = threadIdx.x;

    // A: cp16 [m][k2]
    #pragma unroll
    for (int it = 0; it < 4; it++) {
        int i = tid + it * 512;
        int m  = i >> 4;
        int k4 = i & 15;
        cp16(smem_u32p(&sAhi[m * PAD + k4 * 4]), &g_ahi[(r0 + m) * 64 + k4 * 4]);
        cp16(smem_u32p(&sAlo[m * PAD + k4 * 4]), &g_alo[(r0 + m) * 64 + k4 * 4]);
    }
    // B: cp16 [k2][p] — 4 consecutive pixels per op (aligned: col0 at idx 4)
    #pragma unroll
    for (int it = 0; it < 4; it++) {
        int i = tid + it * 512;            // [0, 2048)
        int k2 = i >> 5;
        int p  = (i & 31) * 4;
        int gp = p0 + p;
        int row = gp / 96;
        int col = gp - row * 96;
        int src = ((n * IN_CI + k2) * IN_R + row + 1) * IN_CSTR + col + 4;
        cp16(smem_u32p(&sBhi[k2 * PADB + p]), &g_inhi[src]);
        cp16(smem_u32p(&sBlo[k2 * PADB + p]), &g_inlo[src]);
    }
    cp_commit();
    cp_wait<0>();
    __syncthreads();

    const int wid = tid >> 5;
    const int lane = tid & 31;
    const int wm = wid & 3;
    const int wn = wid >> 2;
    const int r  = lane >> 2;
    const int q  = lane & 3;

    float d[2][4][4];
    #pragma unroll
    for (int mi = 0; mi < 2; mi++)
        #pragma unroll
        for (int ni = 0; ni < 4; ni++)
            #pragma unroll
            for (int e = 0; e < 4; e++) d[mi][ni][e] = 0.f;

    #pragma unroll
    for (int ks = 0; ks < 8; ks++) {
        const int kc = ks * 8;
        u32 ahi[2][4], alo[2][4];
        #pragma unroll
        for (int mi = 0; mi < 2; mi++) {
            const int ra = wm * 32 + mi * 16 + r;
            ahi[mi][0] = sAhi[ra * PAD + kc + q];
            ahi[mi][1] = sAhi[(ra + 8) * PAD + kc + q];
            ahi[mi][2] = sAhi[ra * PAD + kc + 4 + q];
            ahi[mi][3] = sAhi[(ra + 8) * PAD + kc + 4 + q];
            alo[mi][0] = sAlo[ra * PAD + kc + q];
            alo[mi][1] = sAlo[(ra + 8) * PAD + kc + q];
            alo[mi][2] = sAlo[ra * PAD + kc + 4 + q];
            alo[mi][3] = sAlo[(ra + 8) * PAD + kc + 4 + q];
        }
        #pragma unroll
        for (int ni = 0; ni < 4; ni++) {
            const int nb = wn * 32 + ni * 8 + r;
            u32 bhi0 = sBhi[(kc + q) * PADB + nb];
            u32 bhi1 = sBhi[(kc + 4 + q) * PADB + nb];
            u32 blo0 = sBlo[(kc + q) * PADB + nb];
            u32 blo1 = sBlo[(kc + 4 + q) * PADB + nb];
            #pragma unroll
            for (int mi = 0; mi < 2; mi++) {
                mma_bf16(d[mi][ni], ahi[mi], bhi0, bhi1);
                mma_bf16(d[mi][ni], ahi[mi], blo0, blo1);
                mma_bf16(d[mi][ni], alo[mi], bhi0, bhi1);
            }
        }
    }

    float* Vn = g_v + (size_t)n * K768 * HW;
    #pragma unroll
    for (int mi = 0; mi < 2; mi++) {
        const int row = r0 + wm * 32 + mi * 16 + r;
        #pragma unroll
        for (int ni = 0; ni < 4; ni++) {
            const int col = p0 + wn * 32 + ni * 8 + 2 * q;
            *reinterpret_cast<float2*>(&Vn[(size_t)row * HW + col]) =
                make_float2(d[mi][ni][0], d[mi][ni][1]);
            *reinterpret_cast<float2*>(&Vn[(size_t)(row + 8) * HW + col]) =
                make_float2(d[mi][ni][2], d[mi][ni][3]);
        }
    }
}

__global__ __launch_bounds__(512, 1) void k_main(
    const float* __restrict__ b1,
    const float* __restrict__ w2, const float* __restrict__ b2,
    const float* __restrict__ bbuf)
{
    extern __shared__ u32 sm[];
    const int b = blockIdx.x;
    if (b < CONV1_B) {
        const int n  = b / (H / 2);
        const int y0 = (b - n * (H / 2)) * 2;
        conv1_path(sm, n, y0, b1, w2, b2, bbuf);
    } else {
        const int v   = b - CONV1_B;
        const int n   = v / 432;
        const int rem = v - n * 432;
        const int r0  = (rem / 72) * 128;
        const int p0  = (rem - (rem / 72) * 72) * 128;
        vgemm_path(sm, n, r0, p0);
    }
}

// ===========================================================================
// combine (R11 known-good)
// ===========================================================================
__global__ __launch_bounds__(256) void k_combine(
    const float* __restrict__ bias, float* __restrict__ out)
{
    const int p  = blockIdx.x * 256 + threadIdx.x;
    const int cb = blockIdx.y * 16;
    const int n  = p / HW;
    const int hw = p - n * HW;
    const int y  = hw / W;
    const int x  = hw - y * W;

    int  off[9];
    u32  okm = 0;
    #pragma unroll
    for (int l = 0; l < 9; l++) {
        const int dy = l / 3 - 1, dx = l % 3 - 1;
        const bool ok = (unsigned)(y + dy) < (unsigned)H && (unsigned)(x + dx) < (unsigned)W;
        off[l] = ok ? (dy * W + dx) : 0;
        okm |= (ok ? 1u : 0u) << l;
    }

    float acc[16];
    #pragma unroll
    for (int ci = 0; ci < 16; ci++) acc[ci] = 0.f;

    const float* Vn = g_v + (size_t)n * K768 * HW + hw;

    #pragma unroll
    for (int m = 0; m < 6; m++) {
        float bs[9];
        #pragma unroll
        for (int l = 0; l < 9; l++) {
            float t = __ldg(&g_bases[(n * 54 + m * 9 + l) * HW + hw]);
            bs[l] = (okm >> l & 1u) ? t : 0.f;
        }
        const float* Vm = Vn + (size_t)(cb * 6 + m) * HW;
        #pragma unroll
        for (int ci = 0; ci < 16; ci++) {
            const float* row = Vm + (size_t)(ci * 6) * HW;
            float s = 0.f;
            #pragma unroll
            for (int l = 0; l < 9; l++)
                s = fmaf(bs[l], __ldg(row + off[l]), s);
            acc[ci] += s;
        }
    }

    float* on = out + (size_t)n * C * HW + hw;
    #pragma unroll
    for (int ci = 0; ci < 16; ci++)
        on[(size_t)(cb + ci) * HW] = acc[ci] + __ldg(&bias[cb + ci]);
}

// ---------------------------------------------------------------------------
extern "C" void kernel_launch(void* const* d_in, const int* in_sizes, int n_in,
                              void* d_out, int out_size)
{
    const float* feat = (const float*)d_in[0];
    const float* wgt  = (const float*)d_in[1];
    const float* w1   = (const float*)d_in[2];
    const float* b1   = (const float*)d_in[3];
    const float* w2   = (const float*)d_in[4];
    const float* b2   = (const float*)d_in[5];
    const float* bbuf = (const float*)d_in[6];
    const float* coef = (const float*)d_in[7];
    const float* bias = (const float*)d_in[8];
    float* out = (float*)d_out;

    static bool attr_set = false;
    if (!attr_set) {
        cudaFuncSetAttribute(k_main,
                             cudaFuncAttributeMaxDynamicSharedMemorySize, SM_BYTES);
        attr_set = true;
    }

    k_prep<<<PREP_B, 512>>>(feat, wgt, w1, coef);

    k_main<<<MAIN_B, 512, SM_BYTES>>>(b1, w2, b2, bbuf);

    dim3 g4((N * HW) / 256, 8);
    k_combine<<<g4, 256>>>(bias, out);
}